// round 13
// baseline (speedup 1.0000x reference)
#include <cuda_runtime.h>
#include <math.h>

#define BB 16
#define INC 512
#define OUTC 256
#define HH 32
#define WW 32
#define FD 1024
#define DK 128
#define NS 14          // interior samples (B-2)
#define OH 64
#define OW 64

// ---------------- scratch (static device memory; no allocation) ----------------
__device__ float g_mid[NS * INC * FD];
__device__ float g_q[NS * INC * DK];
__device__ float g_kl[NS * INC * DK];
__device__ float g_kr[NS * INC * DK];
__device__ float g_kvl[NS * DK * FD];
__device__ float g_kvr[NS * DK * FD];
__device__ float g_z[2 * NS * INC];
__device__ float g_gate[BB * OUTC * OH * OW];
__device__ float g_y[BB * OUTC * OH * OW];
__device__ float g_bnsum[OUTC];
__device__ float g_bnsq[OUTC];
__device__ float g_bnscale[OUTC];
__device__ float g_bnshift[OUTC];

// ---------------- tf32 mma helpers ----------------
// Raw fp32 bit patterns are fed to the tf32 MMA (HW truncates low mantissa).
__device__ __forceinline__ void mma_tf32(float (&d)[4], const unsigned (&a)[4], const unsigned (&b)[2]) {
    asm("mma.sync.aligned.m16n8k8.row.col.f32.tf32.tf32.f32 "
        "{%0,%1,%2,%3}, {%4,%5,%6,%7}, {%8,%9}, {%0,%1,%2,%3};"
        : "+f"(d[0]), "+f"(d[1]), "+f"(d[2]), "+f"(d[3])
        : "r"(a[0]), "r"(a[1]), "r"(a[2]), "r"(a[3]), "r"(b[0]), "r"(b[1]));
}

__device__ __forceinline__ void cpa16(void* d, const void* s) {
    unsigned sa = (unsigned)__cvta_generic_to_shared(d);
    asm volatile("cp.async.cg.shared.global [%0], [%1], 16;" :: "r"(sa), "l"(s));
}
__device__ __forceinline__ void cpa16z(void* d, const void* s, int sz) {
    unsigned sa = (unsigned)__cvta_generic_to_shared(d);
    asm volatile("cp.async.cg.shared.global [%0], [%1], 16, %2;" :: "r"(sa), "l"(s), "r"(sz));
}
#define CP_COMMIT() asm volatile("cp.async.commit_group;")
#define CP_WAIT0()  asm volatile("cp.async.wait_group 0;")

// ---------------- kernel 1: projections q/kl/kr = phi(A @ W), M-tile 32 ----------------
__global__ __launch_bounds__(256, 2) void proj_mma_kernel(
    const float* __restrict__ x, const float* __restrict__ wq,
    const float* __restrict__ wkl, const float* __restrict__ wkr) {
    int zi = blockIdx.z;
    int sample = zi / 3, p = zi % 3;
    const float* A;
    const float* Wm;
    float* C;
    if (p == 0)      { A = x + (size_t)(sample + 1) * INC * FD; Wm = wq;  C = g_q  + (size_t)sample * INC * DK; }
    else if (p == 1) { A = x + (size_t)(sample + 0) * INC * FD; Wm = wkl; C = g_kl + (size_t)sample * INC * DK; }
    else             { A = x + (size_t)(sample + 2) * INC * FD; Wm = wkr; C = g_kr + (size_t)sample * INC * DK; }

    __shared__ unsigned Asu[2][32 * 20];   // [m][k], stride 20
    __shared__ unsigned Bsu[2][16 * 136];  // [k][n]

    int m0 = blockIdx.x * 32;
    int tid = threadIdx.x;
    int warp = tid >> 5, lane = tid & 31;
    int wm = warp & 1;        // 2 m16 tiles
    int wn = warp >> 1;       // 4 n32 chunks
    int qr = lane >> 2, qc = lane & 3;

    int am = tid >> 2, ak4 = (tid & 3) * 4;  // A fill (threads < 128)

    float acc[4][4] = {};

    if (tid < 128) cpa16(&Asu[0][am * 20 + ak4], &A[(size_t)(m0 + am) * FD + ak4]);
#pragma unroll
    for (int it = 0; it < 2; it++) {
        int e = it * 256 + tid;
        int kk = e >> 5, c4 = (e & 31) * 4;
        cpa16(&Bsu[0][kk * 136 + c4], &Wm[(size_t)kk * DK + c4]);
    }
    CP_COMMIT();

    int pi = 0;
    for (int c = 0; c < 64; c++) {
        CP_WAIT0();
        __syncthreads();
        if (c < 63) {
            int k0 = (c + 1) * 16;
            unsigned* Ad = Asu[pi ^ 1];
            unsigned* Bd = Bsu[pi ^ 1];
            if (tid < 128) cpa16(&Ad[am * 20 + ak4], &A[(size_t)(m0 + am) * FD + k0 + ak4]);
#pragma unroll
            for (int it = 0; it < 2; it++) {
                int e = it * 256 + tid;
                int kk = e >> 5, c4 = (e & 31) * 4;
                cpa16(&Bd[kk * 136 + c4], &Wm[(size_t)(k0 + kk) * DK + c4]);
            }
            CP_COMMIT();
        }
        const unsigned* As = Asu[pi];
        const unsigned* Bs = Bsu[pi];
#pragma unroll
        for (int k8 = 0; k8 < 2; k8++) {
            unsigned a[4];
            int mb = wm * 16 + qr;
            int kb = k8 * 8 + qc;
            a[0] = As[mb * 20 + kb];
            a[1] = As[(mb + 8) * 20 + kb];
            a[2] = As[mb * 20 + kb + 4];
            a[3] = As[(mb + 8) * 20 + kb + 4];
            int rb0 = (k8 * 8 + qc) * 136 + wn * 32 + qr;
            int rb1 = (k8 * 8 + qc + 4) * 136 + wn * 32 + qr;
#pragma unroll
            for (int j = 0; j < 4; j++) {
                unsigned b[2] = {Bs[rb0 + j * 8], Bs[rb1 + j * 8]};
                mma_tf32(acc[j], a, b);
            }
        }
        pi ^= 1;
    }
    // epilogue: phi = elu + 1
#pragma unroll
    for (int half = 0; half < 2; half++) {
        int m = m0 + wm * 16 + half * 8 + qr;
#pragma unroll
        for (int j = 0; j < 4; j++) {
#pragma unroll
            for (int cc = 0; cc < 2; cc++) {
                int ncol = wn * 32 + j * 8 + qc * 2 + cc;
                float v = acc[j][half * 2 + cc];
                C[(size_t)m * DK + ncol] = (v > 0.f) ? (v + 1.f) : expf(v);
            }
        }
    }
}

// ---------------- kernel 2: column sums + z = q @ ksum + 1e-6 ----------------
__global__ void sumz_kernel() {
    int sample = blockIdx.x;
    int side = blockIdx.y;
    const float* K = (side == 0 ? g_kl : g_kr) + (size_t)sample * INC * DK;
    const float* Q = g_q + (size_t)sample * INC * DK;
    __shared__ float ssum[DK];
    int t = threadIdx.x;
    float s = 0.f;
    for (int n = 0; n < INC; n++) s += K[n * DK + t];
    ssum[t] = s;
    __syncthreads();
    float* Z = g_z + (size_t)(side * NS + sample) * INC;
    for (int rr = 0; rr < 4; rr++) {
        int row = rr * 128 + t;
        float d = 0.f;
        for (int k = 0; k < DK; k++) d += Q[row * DK + k] * ssum[k];
        Z[row] = d + 1e-6f;
    }
}

// ---------------- kernel 3: kv[k][d] = sum_n K[n][k] * V[n][d] (R10 config) ----------------
__global__ __launch_bounds__(256, 2) void kv_mma_kernel(const float* __restrict__ x) {
    int zi = blockIdx.z;
    int sample = zi >> 1, side = zi & 1;
    const float* K = (side == 0 ? g_kl : g_kr) + (size_t)sample * INC * DK;
    const float* V = x + (size_t)(sample + (side == 0 ? 0 : 2)) * INC * FD;
    float* C = (side == 0 ? g_kvl : g_kvr) + (size_t)sample * DK * FD;

    __shared__ unsigned Asu[2][16 * 72];
    __shared__ unsigned Bsu[2][16 * 264];

    int m0 = blockIdx.x * 64;
    int n0 = blockIdx.y * 256;
    int tid = threadIdx.x;
    int warp = tid >> 5, lane = tid & 31;
    int wm = warp & 1, wn = warp >> 1;
    int qr = lane >> 2, qc = lane & 3;

    float acc[2][8][4] = {};

    {
        int nn = tid >> 4, k4 = (tid & 15) * 4;
        cpa16(&Asu[0][nn * 72 + k4], &K[(size_t)nn * DK + m0 + k4]);
    }
#pragma unroll
    for (int it = 0; it < 4; it++) {
        int e = it * 256 + tid;
        int nn = e >> 6, c4 = (e & 63) * 4;
        cpa16(&Bsu[0][nn * 264 + c4], &V[(size_t)nn * FD + n0 + c4]);
    }
    CP_COMMIT();

    int pi = 0;
    for (int c = 0; c < 32; c++) {
        CP_WAIT0();
        __syncthreads();
        if (c < 31) {
            int c0 = (c + 1) * 16;
            unsigned* Ad = Asu[pi ^ 1];
            unsigned* Bd = Bsu[pi ^ 1];
            {
                int nn = tid >> 4, k4 = (tid & 15) * 4;
                cpa16(&Ad[nn * 72 + k4], &K[(size_t)(c0 + nn) * DK + m0 + k4]);
            }
#pragma unroll
            for (int it = 0; it < 4; it++) {
                int e = it * 256 + tid;
                int nn = e >> 6, c4 = (e & 63) * 4;
                cpa16(&Bd[nn * 264 + c4], &V[(size_t)(c0 + nn) * FD + n0 + c4]);
            }
            CP_COMMIT();
        }
        const unsigned* As = Asu[pi];
        const unsigned* Bs = Bsu[pi];
#pragma unroll
        for (int k8 = 0; k8 < 2; k8++) {
            unsigned a[2][4];
            int ra0 = (k8 * 8 + qc) * 72;
            int ra1 = (k8 * 8 + qc + 4) * 72;
#pragma unroll
            for (int mi = 0; mi < 2; mi++) {
                int mb = wm * 32 + mi * 16 + qr;
                a[mi][0] = As[ra0 + mb];
                a[mi][1] = As[ra0 + mb + 8];
                a[mi][2] = As[ra1 + mb];
                a[mi][3] = As[ra1 + mb + 8];
            }
            int rb0 = (k8 * 8 + qc) * 264 + wn * 64 + qr;
            int rb1 = (k8 * 8 + qc + 4) * 264 + wn * 64 + qr;
#pragma unroll
            for (int j = 0; j < 8; j++) {
                unsigned b[2] = {Bs[rb0 + j * 8], Bs[rb1 + j * 8]};
                mma_tf32(acc[0][j], a[0], b);
                mma_tf32(acc[1][j], a[1], b);
            }
        }
        pi ^= 1;
    }
#pragma unroll
    for (int mi = 0; mi < 2; mi++) {
#pragma unroll
        for (int half = 0; half < 2; half++) {
            int m = m0 + wm * 32 + mi * 16 + half * 8 + qr;
#pragma unroll
            for (int j = 0; j < 8; j++) {
#pragma unroll
                for (int cc = 0; cc < 2; cc++) {
                    int d = n0 + wn * 64 + j * 8 + qc * 2 + cc;
                    C[(size_t)m * FD + d] = acc[mi][j][half * 2 + cc];
                }
            }
        }
    }
}

// ------ kernel 4: out = x + (q@kvl)/zl + (q@kvr)/zr, dual-B tf32 mma (R12 config) ------
__global__ __launch_bounds__(256, 2) void attnout_mma_kernel(const float* __restrict__ x) {
    __shared__ unsigned AsuB[2][64 * 20];
    __shared__ unsigned BluB[2][16 * 136];
    __shared__ unsigned BruB[2][16 * 136];

    int sample = blockIdx.z;
    const float* Q = g_q + (size_t)sample * INC * DK;
    const float* KVL = g_kvl + (size_t)sample * DK * FD;
    const float* KVR = g_kvr + (size_t)sample * DK * FD;
    const float* Zl = g_z + (size_t)sample * INC;
    const float* Zr = g_z + (size_t)(NS + sample) * INC;
    const float* X = x + (size_t)(sample + 1) * INC * FD;
    float* C = g_mid + (size_t)sample * INC * FD;

    int m0 = blockIdx.x * 64;
    int n0 = blockIdx.y * 128;
    int tid = threadIdx.x;
    int warp = tid >> 5, lane = tid & 31;
    int wm = warp & 1, wn = warp >> 1;
    int qr = lane >> 2, qc = lane & 3;

    int am = tid >> 2, ak4 = (tid & 3) * 4;

    float accl[2][4][4] = {}, accr[2][4][4] = {};

    cpa16(&AsuB[0][am * 20 + ak4], &Q[(size_t)(m0 + am) * DK + ak4]);
#pragma unroll
    for (int it = 0; it < 2; it++) {
        int e = it * 256 + tid;
        int kk = e >> 5, c4 = (e & 31) * 4;
        cpa16(&BluB[0][kk * 136 + c4], &KVL[(size_t)kk * FD + n0 + c4]);
        cpa16(&BruB[0][kk * 136 + c4], &KVR[(size_t)kk * FD + n0 + c4]);
    }
    CP_COMMIT();

    int pi = 0;
    for (int c = 0; c < 8; c++) {
        CP_WAIT0();
        __syncthreads();
        if (c < 7) {
            int k0 = (c + 1) * 16;
            unsigned* Ad = AsuB[pi ^ 1];
            unsigned* Bld = BluB[pi ^ 1];
            unsigned* Brd = BruB[pi ^ 1];
            cpa16(&Ad[am * 20 + ak4], &Q[(size_t)(m0 + am) * DK + k0 + ak4]);
#pragma unroll
            for (int it = 0; it < 2; it++) {
                int e = it * 256 + tid;
                int kk = e >> 5, c4 = (e & 31) * 4;
                cpa16(&Bld[kk * 136 + c4], &KVL[(size_t)(k0 + kk) * FD + n0 + c4]);
                cpa16(&Brd[kk * 136 + c4], &KVR[(size_t)(k0 + kk) * FD + n0 + c4]);
            }
            CP_COMMIT();
        }
        const unsigned* As = AsuB[pi];
        const unsigned* Bl = BluB[pi];
        const unsigned* Br = BruB[pi];
#pragma unroll
        for (int k8 = 0; k8 < 2; k8++) {
            unsigned a[2][4];
            int kb = k8 * 8 + qc;
#pragma unroll
            for (int mi = 0; mi < 2; mi++) {
                int mb = wm * 32 + mi * 16 + qr;
                a[mi][0] = As[mb * 20 + kb];
                a[mi][1] = As[(mb + 8) * 20 + kb];
                a[mi][2] = As[mb * 20 + kb + 4];
                a[mi][3] = As[(mb + 8) * 20 + kb + 4];
            }
            int rb0 = (k8 * 8 + qc) * 136 + wn * 32 + qr;
            int rb1 = (k8 * 8 + qc + 4) * 136 + wn * 32 + qr;
#pragma unroll
            for (int j = 0; j < 4; j++) {
                unsigned bl[2] = {Bl[rb0 + j * 8], Bl[rb1 + j * 8]};
                unsigned br[2] = {Br[rb0 + j * 8], Br[rb1 + j * 8]};
                mma_tf32(accl[0][j], a[0], bl);
                mma_tf32(accl[1][j], a[1], bl);
                mma_tf32(accr[0][j], a[0], br);
                mma_tf32(accr[1][j], a[1], br);
            }
        }
        pi ^= 1;
    }
#pragma unroll
    for (int mi = 0; mi < 2; mi++) {
#pragma unroll
        for (int half = 0; half < 2; half++) {
            int m = m0 + wm * 32 + mi * 16 + half * 8 + qr;
            float zl = Zl[m], zr = Zr[m];
#pragma unroll
            for (int j = 0; j < 4; j++) {
#pragma unroll
                for (int cc = 0; cc < 2; cc++) {
                    int d = n0 + wn * 32 + j * 8 + qc * 2 + cc;
                    C[(size_t)m * FD + d] = X[(size_t)m * FD + d]
                        + accl[mi][j][half * 2 + cc] / zl
                        + accr[mi][j][half * 2 + cc] / zr;
                }
            }
        }
    }
}

// ------ kernel 5: ConvTranspose 2x2 s2 via tf32 mma + fused gate ------
// M-tile 128 x N-tile 256, 1 CTA/SM, dynamic smem, 1:1 LDS:mma.
#define CTA_ 2176   // 16*136 words per A buffer
#define CTB_ 4224   // 16*264 words per B buffer
__global__ __launch_bounds__(256) void convt_mma_kernel(
    const float* __restrict__ x, const float* __restrict__ upw,
    const float* __restrict__ upb, const float* __restrict__ s) {
    extern __shared__ unsigned cvs[];
    unsigned* Au = cvs;            // 2 * CTA_
    unsigned* Bu = cvs + 2 * CTA_; // 2 * CTB_

    int n = blockIdx.z;
    const float* src = (n == 0) ? x
                     : (n == BB - 1) ? (x + (size_t)(BB - 1) * INC * FD)
                     : (g_mid + (size_t)(n - 1) * INC * FD);
    int m0 = blockIdx.x * 128;
    int n0 = blockIdx.y * 256;

    int tid = threadIdx.x;
    int warp = tid >> 5, lane = tid & 31;
    int wm = warp & 1;        // m half (64 each)
    int wn = warp >> 1;       // n64 chunk
    int qr = lane >> 2;
    int qc = lane & 3;

    float acc[4][8][4] = {};

    // issue chunk 0: A 16x128 ([k][m] stride 136), B 16x256 ([k][n] stride 264)
#pragma unroll
    for (int it = 0; it < 2; it++) {
        int e = it * 256 + tid;
        int cc = e >> 5, m4 = (e & 31) * 4;
        cpa16(&Au[cc * 136 + m4], &upw[(size_t)cc * 1024 + m0 + m4]);
    }
#pragma unroll
    for (int it = 0; it < 4; it++) {
        int e = it * 256 + tid;
        int cc = e >> 6, c4 = (e & 63) * 4;
        cpa16(&Bu[cc * 264 + c4], &src[(size_t)cc * FD + n0 + c4]);
    }
    CP_COMMIT();

    int pi = 0;
    for (int c = 0; c < 32; c++) {
        CP_WAIT0();
        __syncthreads();
        if (c < 31) {
            int c0 = (c + 1) * 16;
            unsigned* Ad = Au + (pi ? 0 : CTA_);
            unsigned* Bd = Bu + (pi ? 0 : CTB_);
#pragma unroll
            for (int it = 0; it < 2; it++) {
                int e = it * 256 + tid;
                int cc = e >> 5, m4 = (e & 31) * 4;
                cpa16(&Ad[cc * 136 + m4], &upw[(size_t)(c0 + cc) * 1024 + m0 + m4]);
            }
#pragma unroll
            for (int it = 0; it < 4; it++) {
                int e = it * 256 + tid;
                int cc = e >> 6, c4 = (e & 63) * 4;
                cpa16(&Bd[cc * 264 + c4], &src[(size_t)(c0 + cc) * FD + n0 + c4]);
            }
            CP_COMMIT();
        }
        const unsigned* As = Au + (pi ? CTA_ : 0);
        const unsigned* Bs = Bu + (pi ? CTB_ : 0);
#pragma unroll
        for (int k8 = 0; k8 < 2; k8++) {
            unsigned a[4][4];
            int ra0 = (k8 * 8 + qc) * 136;
            int ra1 = (k8 * 8 + qc + 4) * 136;
#pragma unroll
            for (int mi = 0; mi < 4; mi++) {
                int mb = wm * 64 + mi * 16 + qr;
                a[mi][0] = As[ra0 + mb];
                a[mi][1] = As[ra0 + mb + 8];
                a[mi][2] = As[ra1 + mb];
                a[mi][3] = As[ra1 + mb + 8];
            }
            int rb0 = (k8 * 8 + qc) * 264 + wn * 64 + qr;
            int rb1 = (k8 * 8 + qc + 4) * 264 + wn * 64 + qr;
#pragma unroll
            for (int j = 0; j < 8; j++) {
                unsigned b[2] = {Bs[rb0 + j * 8], Bs[rb1 + j * 8]};
                mma_tf32(acc[0][j], a[0], b);
                mma_tf32(acc[1][j], a[1], b);
                mma_tf32(acc[2][j], a[2], b);
                mma_tf32(acc[3][j], a[3], b);
            }
        }
        pi ^= 1;
    }
    // epilogue: bias + skip + relu + sigmoid, scatter to g_gate
#pragma unroll
    for (int mi = 0; mi < 4; mi++) {
#pragma unroll
        for (int half = 0; half < 2; half++) {
            int row = m0 + wm * 64 + mi * 16 + half * 8 + qr;
            int o = row >> 2, ab = row & 3, av = ab >> 1, bq = ab & 1;
            float bias = upb[o];
#pragma unroll
            for (int j = 0; j < 8; j++) {
#pragma unroll
                for (int cc = 0; cc < 2; cc++) {
                    int col = n0 + wn * 64 + j * 8 + qc * 2 + cc;
                    int isp = col >> 5, jsp = col & 31;
                    int oy = 2 * isp + av, ox = 2 * jsp + bq;
                    size_t gi = (((size_t)n * OUTC + o) * OH + oy) * OW + ox;
                    float v = acc[mi][j][half * 2 + cc] + bias + s[gi];
                    v = v > 0.f ? v : 0.f;
                    g_gate[gi] = 1.f / (1.f + expf(-v));
                }
            }
        }
    }
}

// ---------------- kernel 6: conv3x3 via tf32 mma, cp.async pipeline ----------------
#define PS 744
#define INW (8 * PS)
#define WW_ 4864
__global__ __launch_bounds__(256) void conv_mma_kernel(
    const float* __restrict__ sskip, const float* __restrict__ cw,
    const float* __restrict__ cb) {
    extern __shared__ unsigned dyns[];
    unsigned* inb = dyns;
    unsigned* wb = dyns + 2 * INW;
    float* rs = (float*)(dyns + 2 * INW + 2 * WW_);
    float* rq = rs + 64;

    int n = blockIdx.z;
    int oc0 = blockIdx.y * 64;
    int y0 = blockIdx.x * 8;

    int tid = threadIdx.x;
    int warp = tid >> 5, lane = tid & 31;
    int wn = warp;
    int qr = lane >> 2;
    int qc = lane & 3;

    for (int e = tid; e < 320; e += 256) {
        int bsel = e >= 160;
        int r2 = e - bsel * 160;
        int r = r2 >> 1;
        int icc = r / 10, yy = r - icc * 10;
        inb[bsel * INW + icc * PS + yy * 72 + ((r2 & 1) ? 68 : 3)] = 0u;
    }
    if (tid < 64) { rs[tid] = 0.f; rq[tid] = 0.f; }

    float acc[4][8][4] = {};

    int seg = (tid & 15) * 4;
    int rbase = tid >> 4;

#pragma unroll
    for (int i = 0; i < 5; i++) {
        int r = rbase + 16 * i;
        int icc = r / 10, yy = r - icc * 10;
        int gy = y0 + yy - 1;
        int ic = icc;
        int gyc = gy < 0 ? 0 : (gy > OH - 1 ? OH - 1 : gy);
        const float* srcp = (ic < OUTC)
            ? &g_gate[(((size_t)n * OUTC + ic) * OH + gyc) * OW + seg]
            : &sskip[(((size_t)n * OUTC + (ic - OUTC)) * OH + gyc) * OW + seg];
        int sz = ((unsigned)gy < (unsigned)OH) ? 16 : 0;
        cpa16z(&inb[icc * PS + yy * 72 + 4 + seg], srcp, sz);
    }
#pragma unroll
    for (int i = 0; i < 5; i++) {
        int e = tid + 256 * i;
        if (e < 1152) {
            int oc = e / 18, f = e - oc * 18;
            cpa16(&wb[oc * 76 + f * 4], &cw[(size_t)(oc0 + oc) * (2 * OUTC * 9) + f * 4]);
        }
    }
    CP_COMMIT();

    int pi = 0;
    for (int c = 0; c < 64; c++) {
        CP_WAIT0();
        __syncthreads();
        if (c < 63) {
            int ic0 = (c + 1) * 8;
            unsigned* ind = inb + (pi ? 0 : INW);
            unsigned* wd = wb + (pi ? 0 : WW_);
#pragma unroll
            for (int i = 0; i < 5; i++) {
                int r = rbase + 16 * i;
                int icc = r / 10, yy = r - icc * 10;
                int gy = y0 + yy - 1;
                int ic = ic0 + icc;
                int gyc = gy < 0 ? 0 : (gy > OH - 1 ? OH - 1 : gy);
                const float* srcp = (ic < OUTC)
                    ? &g_gate[(((size_t)n * OUTC + ic) * OH + gyc) * OW + seg]
                    : &sskip[(((size_t)n * OUTC + (ic - OUTC)) * OH + gyc) * OW + seg];
                int sz = ((unsigned)gy < (unsigned)OH) ? 16 : 0;
                cpa16z(&ind[icc * PS + yy * 72 + 4 + seg], srcp, sz);
            }
#pragma unroll
            for (int i = 0; i < 5; i++) {
                int e = tid + 256 * i;
                if (e < 1152) {
                    int oc = e / 18, f = e - oc * 18;
                    cpa16(&wd[oc * 76 + f * 4], &cw[(size_t)(oc0 + oc) * (2 * OUTC * 9) + ic0 * 9 + f * 4]);
                }
            }
            CP_COMMIT();
        }
        const unsigned* in_s = inb + (pi ? INW : 0);
        const unsigned* w_s = wb + (pi ? WW_ : 0);
#pragma unroll
        for (int ky = 0; ky < 3; ky++) {
            int rowoff = (wn + ky) * 72 + 3;
#pragma unroll
            for (int kx = 0; kx < 3; kx++) {
                int pos = ky * 3 + kx;
                unsigned a[4][4];
#pragma unroll
                for (int mi = 0; mi < 4; mi++) {
                    int ocb = mi * 16 + qr;
                    a[mi][0] = w_s[ocb * 76 + qc * 9 + pos];
                    a[mi][1] = w_s[(ocb + 8) * 76 + qc * 9 + pos];
                    a[mi][2] = w_s[ocb * 76 + (qc + 4) * 9 + pos];
                    a[mi][3] = w_s[(ocb + 8) * 76 + (qc + 4) * 9 + pos];
                }
#pragma unroll
                for (int j = 0; j < 8; j++) {
                    int col = j * 8 + qr + kx;
                    unsigned b[2] = {in_s[qc * PS + rowoff + col],
                                     in_s[(qc + 4) * PS + rowoff + col]};
                    mma_tf32(acc[0][j], a[0], b);
                    mma_tf32(acc[1][j], a[1], b);
                    mma_tf32(acc[2][j], a[2], b);
                    mma_tf32(acc[3][j], a[3], b);
                }
            }
        }
        pi ^= 1;
    }

    int row = y0 + wn;
#pragma unroll
    for (int mi = 0; mi < 4; mi++) {
#pragma unroll
        for (int half = 0; half < 2; half++) {
            int ocl = mi * 16 + half * 8 + qr;
            int oc = oc0 + ocl;
            float bias = cb[oc];
            float s0 = 0.f, s1 = 0.f;
#pragma unroll
            for (int j = 0; j < 8; j++) {
#pragma unroll
                for (int cc = 0; cc < 2; cc++) {
                    float v = acc[mi][j][half * 2 + cc] + bias;
                    int col = j * 8 + qc * 2 + cc;
                    g_y[(((size_t)n * OUTC + oc) * OH + row) * OW + col] = v;
                    s0 += v;
                    s1 += v * v;
                }
            }
            s0 += __shfl_xor_sync(0xffffffffu, s0, 1);
            s0 += __shfl_xor_sync(0xffffffffu, s0, 2);
            s1 += __shfl_xor_sync(0xffffffffu, s1, 1);
            s1 += __shfl_xor_sync(0xffffffffu, s1, 2);
            if (qc == 0) {
                atomicAdd(&rs[ocl], s0);
                atomicAdd(&rq[ocl], s1);
            }
        }
    }
    __syncthreads();
    if (tid < 64) {
        atomicAdd(&g_bnsum[oc0 + tid], rs[tid]);
        atomicAdd(&g_bnsq[oc0 + tid], rq[tid]);
    }
}

// ---------------- small kernels ----------------
__global__ void zero_kernel() {
    int t = threadIdx.x;
    g_bnsum[t] = 0.f;
    g_bnsq[t] = 0.f;
}

__global__ void bnstats_kernel(const float* __restrict__ bn_g, const float* __restrict__ bn_b) {
    int c = threadIdx.x;
    float cnt = (float)(BB * OH * OW);
    float mean = g_bnsum[c] / cnt;
    float var = g_bnsq[c] / cnt - mean * mean;
    float inv = rsqrtf(var + 1e-5f);
    float sc = bn_g[c] * inv;
    g_bnscale[c] = sc;
    g_bnshift[c] = bn_b[c] - mean * sc;
}

__global__ void bnorm_kernel(float* __restrict__ out) {
    int i4 = blockIdx.x * blockDim.x + threadIdx.x;
    const int total4 = BB * OUTC * OH * OW / 4;
    if (i4 >= total4) return;
    int base = i4 * 4;
    int oc = (base >> 12) & (OUTC - 1);
    float sc = g_bnscale[oc], sh = g_bnshift[oc];
    float4 v = *(const float4*)&g_y[base];
    float4 r;
    r.x = fmaxf(v.x * sc + sh, 0.f);
    r.y = fmaxf(v.y * sc + sh, 0.f);
    r.z = fmaxf(v.z * sc + sh, 0.f);
    r.w = fmaxf(v.w * sc + sh, 0.f);
    *(float4*)&out[base] = r;
}

// ---------------- launcher ----------------
extern "C" void kernel_launch(void* const* d_in, const int* in_sizes, int n_in,
                              void* d_out, int out_size) {
    const float* x    = (const float*)d_in[0];
    const float* s    = (const float*)d_in[1];
    const float* up_w = (const float*)d_in[2];
    const float* up_b = (const float*)d_in[3];
    const float* wq   = (const float*)d_in[4];
    const float* wkl  = (const float*)d_in[5];
    const float* wkr  = (const float*)d_in[6];
    const float* c1_w = (const float*)d_in[7];
    const float* c1_b = (const float*)d_in[8];
    const float* bn_g = (const float*)d_in[9];
    const float* bn_b = (const float*)d_in[10];
    float* out = (float*)d_out;

    const int conv_smem = (2 * INW + 2 * WW_) * 4 + 128 * 4;  // 87040 bytes
    cudaFuncSetAttribute(conv_mma_kernel,
                         cudaFuncAttributeMaxDynamicSharedMemorySize, conv_smem);
    const int cvt_smem = (2 * CTA_ + 2 * CTB_) * 4;           // 51200 bytes
    cudaFuncSetAttribute(convt_mma_kernel,
                         cudaFuncAttributeMaxDynamicSharedMemorySize, cvt_smem);

    proj_mma_kernel<<<dim3(16, 1, NS * 3), 256>>>(x, wq, wkl, wkr);
    sumz_kernel<<<dim3(NS, 2), 128>>>();
    kv_mma_kernel<<<dim3(2, 4, NS * 2), 256>>>(x);
    attnout_mma_kernel<<<dim3(8, 8, NS), 256>>>(x);
    convt_mma_kernel<<<dim3(8, 4, BB), 256, cvt_smem>>>(x, up_w, up_b, s);
    zero_kernel<<<1, OUTC>>>();
    conv_mma_kernel<<<dim3(8, 4, BB), 256, conv_smem>>>(s, c1_w, c1_b);
    bnstats_kernel<<<1, OUTC>>>(bn_g, bn_b);
    int total4 = BB * OUTC * OH * OW / 4;
    bnorm_kernel<<<(total4 + 255) / 256, 256>>>(out);
}

// round 14
// speedup vs baseline: 1.0673x; 1.0673x over previous
#include <cuda_runtime.h>
#include <math.h>

#define BB 16
#define INC 512
#define OUTC 256
#define HH 32
#define WW 32
#define FD 1024
#define DK 128
#define NS 14          // interior samples (B-2)
#define OH 64
#define OW 64

// ---------------- scratch (static device memory; no allocation) ----------------
__device__ float g_mid[NS * INC * FD];
__device__ float g_q[NS * INC * DK];
__device__ float g_kl[NS * INC * DK];
__device__ float g_kr[NS * INC * DK];
__device__ float g_kvl[NS * DK * FD];
__device__ float g_kvr[NS * DK * FD];
__device__ float g_z[2 * NS * INC];
__device__ float g_gate[BB * OUTC * OH * OW];
__device__ float g_y[BB * OUTC * OH * OW];
__device__ float g_bnsum[OUTC];
__device__ float g_bnsq[OUTC];
__device__ float g_bnscale[OUTC];
__device__ float g_bnshift[OUTC];

// ---------------- tf32 mma helpers ----------------
// Raw fp32 bit patterns are fed to the tf32 MMA (HW truncates low mantissa).
__device__ __forceinline__ void mma_tf32(float (&d)[4], const unsigned (&a)[4], const unsigned (&b)[2]) {
    asm("mma.sync.aligned.m16n8k8.row.col.f32.tf32.tf32.f32 "
        "{%0,%1,%2,%3}, {%4,%5,%6,%7}, {%8,%9}, {%0,%1,%2,%3};"
        : "+f"(d[0]), "+f"(d[1]), "+f"(d[2]), "+f"(d[3])
        : "r"(a[0]), "r"(a[1]), "r"(a[2]), "r"(a[3]), "r"(b[0]), "r"(b[1]));
}

__device__ __forceinline__ void cpa16(void* d, const void* s) {
    unsigned sa = (unsigned)__cvta_generic_to_shared(d);
    asm volatile("cp.async.cg.shared.global [%0], [%1], 16;" :: "r"(sa), "l"(s));
}
__device__ __forceinline__ void cpa16z(void* d, const void* s, int sz) {
    unsigned sa = (unsigned)__cvta_generic_to_shared(d);
    asm volatile("cp.async.cg.shared.global [%0], [%1], 16, %2;" :: "r"(sa), "l"(s), "r"(sz));
}
#define CP_COMMIT() asm volatile("cp.async.commit_group;")
#define CP_WAIT0()  asm volatile("cp.async.wait_group 0;")

// ---------------- kernel 1: projections q/kl/kr = phi(A @ W) ----------------
// A tile in smem row-major [m][k], stride 20 (conflict-free), cpa16 fill. M-tile 64.
__global__ __launch_bounds__(256, 2) void proj_mma_kernel(
    const float* __restrict__ x, const float* __restrict__ wq,
    const float* __restrict__ wkl, const float* __restrict__ wkr) {
    int zi = blockIdx.z;
    int sample = zi / 3, p = zi % 3;
    const float* A;
    const float* Wm;
    float* C;
    if (p == 0)      { A = x + (size_t)(sample + 1) * INC * FD; Wm = wq;  C = g_q  + (size_t)sample * INC * DK; }
    else if (p == 1) { A = x + (size_t)(sample + 0) * INC * FD; Wm = wkl; C = g_kl + (size_t)sample * INC * DK; }
    else             { A = x + (size_t)(sample + 2) * INC * FD; Wm = wkr; C = g_kr + (size_t)sample * INC * DK; }

    __shared__ unsigned Asu[2][64 * 20];   // [m][k], stride 20
    __shared__ unsigned Bsu[2][16 * 136];  // [k][n]

    int m0 = blockIdx.x * 64;
    int tid = threadIdx.x;
    int warp = tid >> 5, lane = tid & 31;
    int wm = warp & 3;
    int wn = warp >> 2;
    int qr = lane >> 2, qc = lane & 3;

    int am = tid >> 2, ak4 = (tid & 3) * 4;  // A fill coords

    float acc[8][4] = {};

    cpa16(&Asu[0][am * 20 + ak4], &A[(size_t)(m0 + am) * FD + ak4]);
#pragma unroll
    for (int it = 0; it < 2; it++) {
        int e = it * 256 + tid;
        int kk = e >> 5, c4 = (e & 31) * 4;
        cpa16(&Bsu[0][kk * 136 + c4], &Wm[(size_t)kk * DK + c4]);
    }
    CP_COMMIT();

    int pi = 0;
    for (int c = 0; c < 64; c++) {
        CP_WAIT0();
        __syncthreads();
        if (c < 63) {
            int k0 = (c + 1) * 16;
            unsigned* Ad = Asu[pi ^ 1];
            unsigned* Bd = Bsu[pi ^ 1];
            cpa16(&Ad[am * 20 + ak4], &A[(size_t)(m0 + am) * FD + k0 + ak4]);
#pragma unroll
            for (int it = 0; it < 2; it++) {
                int e = it * 256 + tid;
                int kk = e >> 5, c4 = (e & 31) * 4;
                cpa16(&Bd[kk * 136 + c4], &Wm[(size_t)(k0 + kk) * DK + c4]);
            }
            CP_COMMIT();
        }
        const unsigned* As = Asu[pi];
        const unsigned* Bs = Bsu[pi];
#pragma unroll
        for (int k8 = 0; k8 < 2; k8++) {
            unsigned a[4];
            int mb = wm * 16 + qr;
            int kb = k8 * 8 + qc;
            a[0] = As[mb * 20 + kb];
            a[1] = As[(mb + 8) * 20 + kb];
            a[2] = As[mb * 20 + kb + 4];
            a[3] = As[(mb + 8) * 20 + kb + 4];
            int rb0 = (k8 * 8 + qc) * 136 + wn * 64 + qr;
            int rb1 = (k8 * 8 + qc + 4) * 136 + wn * 64 + qr;
#pragma unroll
            for (int j = 0; j < 8; j++) {
                unsigned b[2] = {Bs[rb0 + j * 8], Bs[rb1 + j * 8]};
                mma_tf32(acc[j], a, b);
            }
        }
        pi ^= 1;
    }
    // epilogue: phi = elu + 1
#pragma unroll
    for (int half = 0; half < 2; half++) {
        int m = m0 + wm * 16 + half * 8 + qr;
#pragma unroll
        for (int j = 0; j < 8; j++) {
#pragma unroll
            for (int cc = 0; cc < 2; cc++) {
                int ncol = wn * 64 + j * 8 + qc * 2 + cc;
                float v = acc[j][half * 2 + cc];
                C[(size_t)m * DK + ncol] = (v > 0.f) ? (v + 1.f) : expf(v);
            }
        }
    }
}

// ---------------- kernel 2: column sums + z = q @ ksum + 1e-6 ----------------
__global__ void sumz_kernel() {
    int sample = blockIdx.x;
    int side = blockIdx.y;
    const float* K = (side == 0 ? g_kl : g_kr) + (size_t)sample * INC * DK;
    const float* Q = g_q + (size_t)sample * INC * DK;
    __shared__ float ssum[DK];
    int t = threadIdx.x;
    float s = 0.f;
    for (int n = 0; n < INC; n++) s += K[n * DK + t];
    ssum[t] = s;
    __syncthreads();
    float* Z = g_z + (size_t)(side * NS + sample) * INC;
    for (int rr = 0; rr < 4; rr++) {
        int row = rr * 128 + t;
        float d = 0.f;
        for (int k = 0; k < DK; k++) d += Q[row * DK + k] * ssum[k];
        Z[row] = d + 1e-6f;
    }
}

// ---------------- kernel 3: kv[k][d] = sum_n K[n][k] * V[n][d] (R10 config) ----------------
__global__ __launch_bounds__(256, 2) void kv_mma_kernel(const float* __restrict__ x) {
    int zi = blockIdx.z;
    int sample = zi >> 1, side = zi & 1;
    const float* K = (side == 0 ? g_kl : g_kr) + (size_t)sample * INC * DK;
    const float* V = x + (size_t)(sample + (side == 0 ? 0 : 2)) * INC * FD;
    float* C = (side == 0 ? g_kvl : g_kvr) + (size_t)sample * DK * FD;

    __shared__ unsigned Asu[2][16 * 72];
    __shared__ unsigned Bsu[2][16 * 264];

    int m0 = blockIdx.x * 64;
    int n0 = blockIdx.y * 256;
    int tid = threadIdx.x;
    int warp = tid >> 5, lane = tid & 31;
    int wm = warp & 1, wn = warp >> 1;
    int qr = lane >> 2, qc = lane & 3;

    float acc[2][8][4] = {};

    {
        int nn = tid >> 4, k4 = (tid & 15) * 4;
        cpa16(&Asu[0][nn * 72 + k4], &K[(size_t)nn * DK + m0 + k4]);
    }
#pragma unroll
    for (int it = 0; it < 4; it++) {
        int e = it * 256 + tid;
        int nn = e >> 6, c4 = (e & 63) * 4;
        cpa16(&Bsu[0][nn * 264 + c4], &V[(size_t)nn * FD + n0 + c4]);
    }
    CP_COMMIT();

    int pi = 0;
    for (int c = 0; c < 32; c++) {
        CP_WAIT0();
        __syncthreads();
        if (c < 31) {
            int c0 = (c + 1) * 16;
            unsigned* Ad = Asu[pi ^ 1];
            unsigned* Bd = Bsu[pi ^ 1];
            {
                int nn = tid >> 4, k4 = (tid & 15) * 4;
                cpa16(&Ad[nn * 72 + k4], &K[(size_t)(c0 + nn) * DK + m0 + k4]);
            }
#pragma unroll
            for (int it = 0; it < 4; it++) {
                int e = it * 256 + tid;
                int nn = e >> 6, c4 = (e & 63) * 4;
                cpa16(&Bd[nn * 264 + c4], &V[(size_t)(c0 + nn) * FD + n0 + c4]);
            }
            CP_COMMIT();
        }
        const unsigned* As = Asu[pi];
        const unsigned* Bs = Bsu[pi];
#pragma unroll
        for (int k8 = 0; k8 < 2; k8++) {
            unsigned a[2][4];
            int ra0 = (k8 * 8 + qc) * 72;
            int ra1 = (k8 * 8 + qc + 4) * 72;
#pragma unroll
            for (int mi = 0; mi < 2; mi++) {
                int mb = wm * 32 + mi * 16 + qr;
                a[mi][0] = As[ra0 + mb];
                a[mi][1] = As[ra0 + mb + 8];
                a[mi][2] = As[ra1 + mb];
                a[mi][3] = As[ra1 + mb + 8];
            }
            int rb0 = (k8 * 8 + qc) * 264 + wn * 64 + qr;
            int rb1 = (k8 * 8 + qc + 4) * 264 + wn * 64 + qr;
#pragma unroll
            for (int j = 0; j < 8; j++) {
                unsigned b[2] = {Bs[rb0 + j * 8], Bs[rb1 + j * 8]};
                mma_tf32(acc[0][j], a[0], b);
                mma_tf32(acc[1][j], a[1], b);
            }
        }
        pi ^= 1;
    }
#pragma unroll
    for (int mi = 0; mi < 2; mi++) {
#pragma unroll
        for (int half = 0; half < 2; half++) {
            int m = m0 + wm * 32 + mi * 16 + half * 8 + qr;
#pragma unroll
            for (int j = 0; j < 8; j++) {
#pragma unroll
                for (int cc = 0; cc < 2; cc++) {
                    int d = n0 + wn * 64 + j * 8 + qc * 2 + cc;
                    C[(size_t)m * FD + d] = acc[mi][j][half * 2 + cc];
                }
            }
        }
    }
}

// ------ kernel 4: out = x + (q@kvl)/zl + (q@kvr)/zr, dual-B tf32 mma (R12 config) ------
__global__ __launch_bounds__(256, 2) void attnout_mma_kernel(const float* __restrict__ x) {
    __shared__ unsigned AsuB[2][64 * 20];
    __shared__ unsigned BluB[2][16 * 136];
    __shared__ unsigned BruB[2][16 * 136];

    int sample = blockIdx.z;
    const float* Q = g_q + (size_t)sample * INC * DK;
    const float* KVL = g_kvl + (size_t)sample * DK * FD;
    const float* KVR = g_kvr + (size_t)sample * DK * FD;
    const float* Zl = g_z + (size_t)sample * INC;
    const float* Zr = g_z + (size_t)(NS + sample) * INC;
    const float* X = x + (size_t)(sample + 1) * INC * FD;
    float* C = g_mid + (size_t)sample * INC * FD;

    int m0 = blockIdx.x * 64;
    int n0 = blockIdx.y * 128;
    int tid = threadIdx.x;
    int warp = tid >> 5, lane = tid & 31;
    int wm = warp & 1, wn = warp >> 1;
    int qr = lane >> 2, qc = lane & 3;

    int am = tid >> 2, ak4 = (tid & 3) * 4;

    float accl[2][4][4] = {}, accr[2][4][4] = {};

    cpa16(&AsuB[0][am * 20 + ak4], &Q[(size_t)(m0 + am) * DK + ak4]);
#pragma unroll
    for (int it = 0; it < 2; it++) {
        int e = it * 256 + tid;
        int kk = e >> 5, c4 = (e & 31) * 4;
        cpa16(&BluB[0][kk * 136 + c4], &KVL[(size_t)kk * FD + n0 + c4]);
        cpa16(&BruB[0][kk * 136 + c4], &KVR[(size_t)kk * FD + n0 + c4]);
    }
    CP_COMMIT();

    int pi = 0;
    for (int c = 0; c < 8; c++) {
        CP_WAIT0();
        __syncthreads();
        if (c < 7) {
            int k0 = (c + 1) * 16;
            unsigned* Ad = AsuB[pi ^ 1];
            unsigned* Bld = BluB[pi ^ 1];
            unsigned* Brd = BruB[pi ^ 1];
            cpa16(&Ad[am * 20 + ak4], &Q[(size_t)(m0 + am) * DK + k0 + ak4]);
#pragma unroll
            for (int it = 0; it < 2; it++) {
                int e = it * 256 + tid;
                int kk = e >> 5, c4 = (e & 31) * 4;
                cpa16(&Bld[kk * 136 + c4], &KVL[(size_t)(k0 + kk) * FD + n0 + c4]);
                cpa16(&Brd[kk * 136 + c4], &KVR[(size_t)(k0 + kk) * FD + n0 + c4]);
            }
            CP_COMMIT();
        }
        const unsigned* As = AsuB[pi];
        const unsigned* Bl = BluB[pi];
        const unsigned* Br = BruB[pi];
#pragma unroll
        for (int k8 = 0; k8 < 2; k8++) {
            unsigned a[2][4];
            int kb = k8 * 8 + qc;
#pragma unroll
            for (int mi = 0; mi < 2; mi++) {
                int mb = wm * 32 + mi * 16 + qr;
                a[mi][0] = As[mb * 20 + kb];
                a[mi][1] = As[(mb + 8) * 20 + kb];
                a[mi][2] = As[mb * 20 + kb + 4];
                a[mi][3] = As[(mb + 8) * 20 + kb + 4];
            }
            int rb0 = (k8 * 8 + qc) * 136 + wn * 32 + qr;
            int rb1 = (k8 * 8 + qc + 4) * 136 + wn * 32 + qr;
#pragma unroll
            for (int j = 0; j < 4; j++) {
                unsigned bl[2] = {Bl[rb0 + j * 8], Bl[rb1 + j * 8]};
                unsigned br[2] = {Br[rb0 + j * 8], Br[rb1 + j * 8]};
                mma_tf32(accl[0][j], a[0], bl);
                mma_tf32(accl[1][j], a[1], bl);
                mma_tf32(accr[0][j], a[0], br);
                mma_tf32(accr[1][j], a[1], br);
            }
        }
        pi ^= 1;
    }
#pragma unroll
    for (int mi = 0; mi < 2; mi++) {
#pragma unroll
        for (int half = 0; half < 2; half++) {
            int m = m0 + wm * 32 + mi * 16 + half * 8 + qr;
            float zl = Zl[m], zr = Zr[m];
#pragma unroll
            for (int j = 0; j < 4; j++) {
#pragma unroll
                for (int cc = 0; cc < 2; cc++) {
                    int d = n0 + wn * 32 + j * 8 + qc * 2 + cc;
                    C[(size_t)m * FD + d] = X[(size_t)m * FD + d]
                        + accl[mi][j][half * 2 + cc] / zl
                        + accr[mi][j][half * 2 + cc] / zr;
                }
            }
        }
    }
}

// ------ kernel 5: ConvTranspose 2x2 s2 via tf32 mma + fused gate (R10 config) ------
// Also zeroes the BN accumulators (replaces the separate zero_kernel launch).
__global__ __launch_bounds__(256, 2) void convt_mma_kernel(
    const float* __restrict__ x, const float* __restrict__ upw,
    const float* __restrict__ upb, const float* __restrict__ s) {
    int n = blockIdx.z;
    const float* src = (n == 0) ? x
                     : (n == BB - 1) ? (x + (size_t)(BB - 1) * INC * FD)
                     : (g_mid + (size_t)(n - 1) * INC * FD);
    int m0 = blockIdx.x * 64;
    int n0 = blockIdx.y * 256;

    // fold zero_kernel: one block clears BN accumulators (conv launches after us)
    if (blockIdx.x == 0 && blockIdx.y == 0 && blockIdx.z == 0) {
        g_bnsum[threadIdx.x] = 0.f;
        g_bnsq[threadIdx.x] = 0.f;
    }

    __shared__ unsigned Asu[2][16 * 72];
    __shared__ unsigned Bsu[2][16 * 264];

    int tid = threadIdx.x;
    int warp = tid >> 5, lane = tid & 31;
    int wm = warp & 1;
    int wn = warp >> 1;
    int qr = lane >> 2;
    int qc = lane & 3;

    float acc[2][8][4] = {};

    {
        int cc = tid >> 4, m4 = (tid & 15) * 4;
        cpa16(&Asu[0][cc * 72 + m4], &upw[(size_t)cc * 1024 + m0 + m4]);
    }
#pragma unroll
    for (int it = 0; it < 4; it++) {
        int e = it * 256 + tid;
        int cc = e >> 6, c4 = (e & 63) * 4;
        cpa16(&Bsu[0][cc * 264 + c4], &src[(size_t)cc * FD + n0 + c4]);
    }
    CP_COMMIT();

    int pi = 0;
    for (int c = 0; c < 32; c++) {
        CP_WAIT0();
        __syncthreads();
        if (c < 31) {
            int c0 = (c + 1) * 16;
            unsigned* Ad = Asu[pi ^ 1];
            unsigned* Bd = Bsu[pi ^ 1];
            {
                int cc = tid >> 4, m4 = (tid & 15) * 4;
                cpa16(&Ad[cc * 72 + m4], &upw[(size_t)(c0 + cc) * 1024 + m0 + m4]);
            }
#pragma unroll
            for (int it = 0; it < 4; it++) {
                int e = it * 256 + tid;
                int cc = e >> 6, c4 = (e & 63) * 4;
                cpa16(&Bd[cc * 264 + c4], &src[(size_t)(c0 + cc) * FD + n0 + c4]);
            }
            CP_COMMIT();
        }
        const unsigned* As = Asu[pi];
        const unsigned* Bs = Bsu[pi];
#pragma unroll
        for (int k8 = 0; k8 < 2; k8++) {
            unsigned a[2][4];
            int ra0 = (k8 * 8 + qc) * 72;
            int ra1 = (k8 * 8 + qc + 4) * 72;
#pragma unroll
            for (int mi = 0; mi < 2; mi++) {
                int ocb = wm * 32 + mi * 16 + qr;
                a[mi][0] = As[ra0 + ocb];
                a[mi][1] = As[ra0 + ocb + 8];
                a[mi][2] = As[ra1 + ocb];
                a[mi][3] = As[ra1 + ocb + 8];
            }
            int rb0 = (k8 * 8 + qc) * 264 + wn * 64 + qr;
            int rb1 = (k8 * 8 + qc + 4) * 264 + wn * 64 + qr;
#pragma unroll
            for (int j = 0; j < 8; j++) {
                unsigned b[2] = {Bs[rb0 + j * 8], Bs[rb1 + j * 8]};
                mma_tf32(acc[0][j], a[0], b);
                mma_tf32(acc[1][j], a[1], b);
            }
        }
        pi ^= 1;
    }
    // epilogue: bias + skip + relu + sigmoid, scatter to g_gate
#pragma unroll
    for (int mi = 0; mi < 2; mi++) {
#pragma unroll
        for (int half = 0; half < 2; half++) {
            int row = m0 + wm * 32 + mi * 16 + half * 8 + qr;
            int o = row >> 2, ab = row & 3, av = ab >> 1, bq = ab & 1;
            float bias = upb[o];
#pragma unroll
            for (int j = 0; j < 8; j++) {
#pragma unroll
                for (int cc = 0; cc < 2; cc++) {
                    int col = n0 + wn * 64 + j * 8 + qc * 2 + cc;
                    int isp = col >> 5, jsp = col & 31;
                    int oy = 2 * isp + av, ox = 2 * jsp + bq;
                    size_t gi = (((size_t)n * OUTC + o) * OH + oy) * OW + ox;
                    float v = acc[mi][j][half * 2 + cc] + bias + s[gi];
                    v = v > 0.f ? v : 0.f;
                    g_gate[gi] = 1.f / (1.f + expf(-v));
                }
            }
        }
    }
}

// ---------------- kernel 6: conv3x3 via tf32 mma, cp.async pipeline ----------------
#define PS 744
#define INW (8 * PS)
#define WW_ 4864
__global__ __launch_bounds__(256) void conv_mma_kernel(
    const float* __restrict__ sskip, const float* __restrict__ cw,
    const float* __restrict__ cb) {
    extern __shared__ unsigned dyns[];
    unsigned* inb = dyns;
    unsigned* wb = dyns + 2 * INW;
    float* rs = (float*)(dyns + 2 * INW + 2 * WW_);
    float* rq = rs + 64;

    int n = blockIdx.z;
    int oc0 = blockIdx.y * 64;
    int y0 = blockIdx.x * 8;

    int tid = threadIdx.x;
    int warp = tid >> 5, lane = tid & 31;
    int wn = warp;
    int qr = lane >> 2;
    int qc = lane & 3;

    for (int e = tid; e < 320; e += 256) {
        int bsel = e >= 160;
        int r2 = e - bsel * 160;
        int r = r2 >> 1;
        int icc = r / 10, yy = r - icc * 10;
        inb[bsel * INW + icc * PS + yy * 72 + ((r2 & 1) ? 68 : 3)] = 0u;
    }
    if (tid < 64) { rs[tid] = 0.f; rq[tid] = 0.f; }

    float acc[4][8][4] = {};

    int seg = (tid & 15) * 4;
    int rbase = tid >> 4;

#pragma unroll
    for (int i = 0; i < 5; i++) {
        int r = rbase + 16 * i;
        int icc = r / 10, yy = r - icc * 10;
        int gy = y0 + yy - 1;
        int ic = icc;
        int gyc = gy < 0 ? 0 : (gy > OH - 1 ? OH - 1 : gy);
        const float* srcp = (ic < OUTC)
            ? &g_gate[(((size_t)n * OUTC + ic) * OH + gyc) * OW + seg]
            : &sskip[(((size_t)n * OUTC + (ic - OUTC)) * OH + gyc) * OW + seg];
        int sz = ((unsigned)gy < (unsigned)OH) ? 16 : 0;
        cpa16z(&inb[icc * PS + yy * 72 + 4 + seg], srcp, sz);
    }
#pragma unroll
    for (int i = 0; i < 5; i++) {
        int e = tid + 256 * i;
        if (e < 1152) {
            int oc = e / 18, f = e - oc * 18;
            cpa16(&wb[oc * 76 + f * 4], &cw[(size_t)(oc0 + oc) * (2 * OUTC * 9) + f * 4]);
        }
    }
    CP_COMMIT();

    int pi = 0;
    for (int c = 0; c < 64; c++) {
        CP_WAIT0();
        __syncthreads();
        if (c < 63) {
            int ic0 = (c + 1) * 8;
            unsigned* ind = inb + (pi ? 0 : INW);
            unsigned* wd = wb + (pi ? 0 : WW_);
#pragma unroll
            for (int i = 0; i < 5; i++) {
                int r = rbase + 16 * i;
                int icc = r / 10, yy = r - icc * 10;
                int gy = y0 + yy - 1;
                int ic = ic0 + icc;
                int gyc = gy < 0 ? 0 : (gy > OH - 1 ? OH - 1 : gy);
                const float* srcp = (ic < OUTC)
                    ? &g_gate[(((size_t)n * OUTC + ic) * OH + gyc) * OW + seg]
                    : &sskip[(((size_t)n * OUTC + (ic - OUTC)) * OH + gyc) * OW + seg];
                int sz = ((unsigned)gy < (unsigned)OH) ? 16 : 0;
                cpa16z(&ind[icc * PS + yy * 72 + 4 + seg], srcp, sz);
            }
#pragma unroll
            for (int i = 0; i < 5; i++) {
                int e = tid + 256 * i;
                if (e < 1152) {
                    int oc = e / 18, f = e - oc * 18;
                    cpa16(&wd[oc * 76 + f * 4], &cw[(size_t)(oc0 + oc) * (2 * OUTC * 9) + ic0 * 9 + f * 4]);
                }
            }
            CP_COMMIT();
        }
        const unsigned* in_s = inb + (pi ? INW : 0);
        const unsigned* w_s = wb + (pi ? WW_ : 0);
#pragma unroll
        for (int ky = 0; ky < 3; ky++) {
            int rowoff = (wn + ky) * 72 + 3;
#pragma unroll
            for (int kx = 0; kx < 3; kx++) {
                int pos = ky * 3 + kx;
                unsigned a[4][4];
#pragma unroll
                for (int mi = 0; mi < 4; mi++) {
                    int ocb = mi * 16 + qr;
                    a[mi][0] = w_s[ocb * 76 + qc * 9 + pos];
                    a[mi][1] = w_s[(ocb + 8) * 76 + qc * 9 + pos];
                    a[mi][2] = w_s[ocb * 76 + (qc + 4) * 9 + pos];
                    a[mi][3] = w_s[(ocb + 8) * 76 + (qc + 4) * 9 + pos];
                }
#pragma unroll
                for (int j = 0; j < 8; j++) {
                    int col = j * 8 + qr + kx;
                    unsigned b[2] = {in_s[qc * PS + rowoff + col],
                                     in_s[(qc + 4) * PS + rowoff + col]};
                    mma_tf32(acc[0][j], a[0], b);
                    mma_tf32(acc[1][j], a[1], b);
                    mma_tf32(acc[2][j], a[2], b);
                    mma_tf32(acc[3][j], a[3], b);
                }
            }
        }
        pi ^= 1;
    }

    int row = y0 + wn;
#pragma unroll
    for (int mi = 0; mi < 4; mi++) {
#pragma unroll
        for (int half = 0; half < 2; half++) {
            int ocl = mi * 16 + half * 8 + qr;
            int oc = oc0 + ocl;
            float bias = cb[oc];
            float s0 = 0.f, s1 = 0.f;
#pragma unroll
            for (int j = 0; j < 8; j++) {
#pragma unroll
                for (int cc = 0; cc < 2; cc++) {
                    float v = acc[mi][j][half * 2 + cc] + bias;
                    int col = j * 8 + qc * 2 + cc;
                    g_y[(((size_t)n * OUTC + oc) * OH + row) * OW + col] = v;
                    s0 += v;
                    s1 += v * v;
                }
            }
            s0 += __shfl_xor_sync(0xffffffffu, s0, 1);
            s0 += __shfl_xor_sync(0xffffffffu, s0, 2);
            s1 += __shfl_xor_sync(0xffffffffu, s1, 1);
            s1 += __shfl_xor_sync(0xffffffffu, s1, 2);
            if (qc == 0) {
                atomicAdd(&rs[ocl], s0);
                atomicAdd(&rq[ocl], s1);
            }
        }
    }
    __syncthreads();
    if (tid < 64) {
        atomicAdd(&g_bnsum[oc0 + tid], rs[tid]);
        atomicAdd(&g_bnsq[oc0 + tid], rq[tid]);
    }
}

// ---------------- small kernels ----------------
__global__ void bnstats_kernel(const float* __restrict__ bn_g, const float* __restrict__ bn_b) {
    int c = threadIdx.x;
    float cnt = (float)(BB * OH * OW);
    float mean = g_bnsum[c] / cnt;
    float var = g_bnsq[c] / cnt - mean * mean;
    float inv = rsqrtf(var + 1e-5f);
    float sc = bn_g[c] * inv;
    g_bnscale[c] = sc;
    g_bnshift[c] = bn_b[c] - mean * sc;
}

__global__ void bnorm_kernel(float* __restrict__ out) {
    int i4 = blockIdx.x * blockDim.x + threadIdx.x;
    const int total4 = BB * OUTC * OH * OW / 4;
    if (i4 >= total4) return;
    int base = i4 * 4;
    int oc = (base >> 12) & (OUTC - 1);
    float sc = g_bnscale[oc], sh = g_bnshift[oc];
    float4 v = *(const float4*)&g_y[base];
    float4 r;
    r.x = fmaxf(v.x * sc + sh, 0.f);
    r.y = fmaxf(v.y * sc + sh, 0.f);
    r.z = fmaxf(v.z * sc + sh, 0.f);
    r.w = fmaxf(v.w * sc + sh, 0.f);
    *(float4*)&out[base] = r;
}

// ---------------- launcher ----------------
extern "C" void kernel_launch(void* const* d_in, const int* in_sizes, int n_in,
                              void* d_out, int out_size) {
    const float* x    = (const float*)d_in[0];
    const float* s    = (const float*)d_in[1];
    const float* up_w = (const float*)d_in[2];
    const float* up_b = (const float*)d_in[3];
    const float* wq   = (const float*)d_in[4];
    const float* wkl  = (const float*)d_in[5];
    const float* wkr  = (const float*)d_in[6];
    const float* c1_w = (const float*)d_in[7];
    const float* c1_b = (const float*)d_in[8];
    const float* bn_g = (const float*)d_in[9];
    const float* bn_b = (const float*)d_in[10];
    float* out = (float*)d_out;

    const int conv_smem = (2 * INW + 2 * WW_) * 4 + 128 * 4;  // 87040 bytes
    cudaFuncSetAttribute(conv_mma_kernel,
                         cudaFuncAttributeMaxDynamicSharedMemorySize, conv_smem);

    proj_mma_kernel<<<dim3(8, 1, NS * 3), 256>>>(x, wq, wkl, wkr);
    sumz_kernel<<<dim3(NS, 2), 128>>>();
    kv_mma_kernel<<<dim3(2, 4, NS * 2), 256>>>(x);
    attnout_mma_kernel<<<dim3(8, 8, NS), 256>>>(x);
    convt_mma_kernel<<<dim3(16, 4, BB), 256>>>(x, up_w, up_b, s);
    conv_mma_kernel<<<dim3(8, 4, BB), 256, conv_smem>>>(s, c1_w, c1_b);
    bnstats_kernel<<<1, OUTC>>>(bn_g, bn_b);
    int total4 = BB * OUTC * OH * OW / 4;
    bnorm_kernel<<<(total4 + 255) / 256, 256>>>(out);
}

// round 15
// speedup vs baseline: 1.1043x; 1.0347x over previous
#include <cuda_runtime.h>
#include <math.h>

#define BB 16
#define INC 512
#define OUTC 256
#define HH 32
#define WW 32
#define FD 1024
#define DK 128
#define NS 14          // interior samples (B-2)
#define OH 64
#define OW 64

// ---------------- scratch (static device memory; no allocation) ----------------
__device__ float g_mid[NS * INC * FD];
__device__ float g_q[NS * INC * DK];
__device__ float g_kl[NS * INC * DK];
__device__ float g_kr[NS * INC * DK];
__device__ float g_kvl[NS * DK * FD];
__device__ float g_kvr[NS * DK * FD];
__device__ float g_z[2 * NS * INC];
__device__ float g_gate[BB * OUTC * OH * OW];
__device__ float g_y[BB * OUTC * OH * OW];
__device__ float g_bnsum[OUTC];
__device__ float g_bnsq[OUTC];
__device__ float g_bnscale[OUTC];
__device__ float g_bnshift[OUTC];

// ---------------- tf32 mma helpers ----------------
// Raw fp32 bit patterns are fed to the tf32 MMA (HW truncates low mantissa).
__device__ __forceinline__ void mma_tf32(float (&d)[4], const unsigned (&a)[4], const unsigned (&b)[2]) {
    asm("mma.sync.aligned.m16n8k8.row.col.f32.tf32.tf32.f32 "
        "{%0,%1,%2,%3}, {%4,%5,%6,%7}, {%8,%9}, {%0,%1,%2,%3};"
        : "+f"(d[0]), "+f"(d[1]), "+f"(d[2]), "+f"(d[3])
        : "r"(a[0]), "r"(a[1]), "r"(a[2]), "r"(a[3]), "r"(b[0]), "r"(b[1]));
}

__device__ __forceinline__ void cpa16(void* d, const void* s) {
    unsigned sa = (unsigned)__cvta_generic_to_shared(d);
    asm volatile("cp.async.cg.shared.global [%0], [%1], 16;" :: "r"(sa), "l"(s));
}
__device__ __forceinline__ void cpa16z(void* d, const void* s, int sz) {
    unsigned sa = (unsigned)__cvta_generic_to_shared(d);
    asm volatile("cp.async.cg.shared.global [%0], [%1], 16, %2;" :: "r"(sa), "l"(s), "r"(sz));
}
#define CP_COMMIT() asm volatile("cp.async.commit_group;")
#define CP_WAIT0()  asm volatile("cp.async.wait_group 0;")
#define CP_WAIT1()  asm volatile("cp.async.wait_group 1;")
#define CP_WAIT2()  asm volatile("cp.async.wait_group 2;")

// ---------------- kernel 1: projections q/kl/kr = phi(A @ W), 4-stage pipeline ----------------
#define PJ_A 1280   // 64*20
#define PJ_B 2176   // 16*136
__global__ __launch_bounds__(256, 2) void proj_mma_kernel(
    const float* __restrict__ x, const float* __restrict__ wq,
    const float* __restrict__ wkl, const float* __restrict__ wkr) {
    extern __shared__ unsigned psm[];
    unsigned* Ap = psm;               // 4 * PJ_A
    unsigned* Bp = psm + 4 * PJ_A;    // 4 * PJ_B

    int zi = blockIdx.z;
    int sample = zi / 3, p = zi % 3;
    const float* A;
    const float* Wm;
    float* C;
    if (p == 0)      { A = x + (size_t)(sample + 1) * INC * FD; Wm = wq;  C = g_q  + (size_t)sample * INC * DK; }
    else if (p == 1) { A = x + (size_t)(sample + 0) * INC * FD; Wm = wkl; C = g_kl + (size_t)sample * INC * DK; }
    else             { A = x + (size_t)(sample + 2) * INC * FD; Wm = wkr; C = g_kr + (size_t)sample * INC * DK; }

    int m0 = blockIdx.x * 64;
    int tid = threadIdx.x;
    int warp = tid >> 5, lane = tid & 31;
    int wm = warp & 3;
    int wn = warp >> 2;
    int qr = lane >> 2, qc = lane & 3;

    int am = tid >> 2, ak4 = (tid & 3) * 4;

    float acc[8][4] = {};

    // prologue: issue chunks 0..2
#pragma unroll
    for (int s = 0; s < 3; s++) {
        unsigned* Ad = Ap + s * PJ_A;
        unsigned* Bd = Bp + s * PJ_B;
        cpa16(&Ad[am * 20 + ak4], &A[(size_t)(m0 + am) * FD + s * 16 + ak4]);
#pragma unroll
        for (int it = 0; it < 2; it++) {
            int e = it * 256 + tid;
            int kk = e >> 5, c4 = (e & 31) * 4;
            cpa16(&Bd[kk * 136 + c4], &Wm[(size_t)(s * 16 + kk) * DK + c4]);
        }
        CP_COMMIT();
    }

    int cs = 0;
    for (int c = 0; c < 64; c++) {
        CP_WAIT2();
        __syncthreads();
        if (c + 3 < 64) {
            int es = cs + 3; if (es >= 4) es -= 4;
            int k0 = (c + 3) * 16;
            unsigned* Ad = Ap + es * PJ_A;
            unsigned* Bd = Bp + es * PJ_B;
            cpa16(&Ad[am * 20 + ak4], &A[(size_t)(m0 + am) * FD + k0 + ak4]);
#pragma unroll
            for (int it = 0; it < 2; it++) {
                int e = it * 256 + tid;
                int kk = e >> 5, c4 = (e & 31) * 4;
                cpa16(&Bd[kk * 136 + c4], &Wm[(size_t)(k0 + kk) * DK + c4]);
            }
        }
        CP_COMMIT();
        const unsigned* As = Ap + cs * PJ_A;
        const unsigned* Bs = Bp + cs * PJ_B;
#pragma unroll
        for (int k8 = 0; k8 < 2; k8++) {
            unsigned a[4];
            int mb = wm * 16 + qr;
            int kb = k8 * 8 + qc;
            a[0] = As[mb * 20 + kb];
            a[1] = As[(mb + 8) * 20 + kb];
            a[2] = As[mb * 20 + kb + 4];
            a[3] = As[(mb + 8) * 20 + kb + 4];
            int rb0 = (k8 * 8 + qc) * 136 + wn * 64 + qr;
            int rb1 = (k8 * 8 + qc + 4) * 136 + wn * 64 + qr;
#pragma unroll
            for (int j = 0; j < 8; j++) {
                unsigned b[2] = {Bs[rb0 + j * 8], Bs[rb1 + j * 8]};
                mma_tf32(acc[j], a, b);
            }
        }
        cs = (cs == 3) ? 0 : cs + 1;
    }
    // epilogue: phi = elu + 1
#pragma unroll
    for (int half = 0; half < 2; half++) {
        int m = m0 + wm * 16 + half * 8 + qr;
#pragma unroll
        for (int j = 0; j < 8; j++) {
#pragma unroll
            for (int cc = 0; cc < 2; cc++) {
                int ncol = wn * 64 + j * 8 + qc * 2 + cc;
                float v = acc[j][half * 2 + cc];
                C[(size_t)m * DK + ncol] = (v > 0.f) ? (v + 1.f) : expf(v);
            }
        }
    }
}

// ---------------- kernel 2: column sums + z = q @ ksum + 1e-6 ----------------
__global__ void sumz_kernel() {
    int sample = blockIdx.x;
    int side = blockIdx.y;
    const float* K = (side == 0 ? g_kl : g_kr) + (size_t)sample * INC * DK;
    const float* Q = g_q + (size_t)sample * INC * DK;
    __shared__ float ssum[DK];
    int t = threadIdx.x;
    float s = 0.f;
    for (int n = 0; n < INC; n++) s += K[n * DK + t];
    ssum[t] = s;
    __syncthreads();
    float* Z = g_z + (size_t)(side * NS + sample) * INC;
    for (int rr = 0; rr < 4; rr++) {
        int row = rr * 128 + t;
        float d = 0.f;
        for (int k = 0; k < DK; k++) d += Q[row * DK + k] * ssum[k];
        Z[row] = d + 1e-6f;
    }
}

// ---------------- kernel 3: kv[k][d] = sum_n K[n][k] * V[n][d], 3-stage pipeline ----------------
#define KV_A 1152   // 16*72
#define KV_B 4224   // 16*264
__global__ __launch_bounds__(256, 2) void kv_mma_kernel(const float* __restrict__ x) {
    extern __shared__ unsigned ksm[];
    unsigned* Ap = ksm;               // 3 * KV_A
    unsigned* Bp = ksm + 3 * KV_A;    // 3 * KV_B

    int zi = blockIdx.z;
    int sample = zi >> 1, side = zi & 1;
    const float* K = (side == 0 ? g_kl : g_kr) + (size_t)sample * INC * DK;
    const float* V = x + (size_t)(sample + (side == 0 ? 0 : 2)) * INC * FD;
    float* C = (side == 0 ? g_kvl : g_kvr) + (size_t)sample * DK * FD;

    int m0 = blockIdx.x * 64;
    int n0 = blockIdx.y * 256;
    int tid = threadIdx.x;
    int warp = tid >> 5, lane = tid & 31;
    int wm = warp & 1, wn = warp >> 1;
    int qr = lane >> 2, qc = lane & 3;

    int an = tid >> 4, ak4 = (tid & 15) * 4;

    float acc[2][8][4] = {};

    // prologue: chunks 0,1
#pragma unroll
    for (int s = 0; s < 2; s++) {
        unsigned* Ad = Ap + s * KV_A;
        unsigned* Bd = Bp + s * KV_B;
        cpa16(&Ad[an * 72 + ak4], &K[(size_t)(s * 16 + an) * DK + m0 + ak4]);
#pragma unroll
        for (int it = 0; it < 4; it++) {
            int e = it * 256 + tid;
            int nn = e >> 6, c4 = (e & 63) * 4;
            cpa16(&Bd[nn * 264 + c4], &V[(size_t)(s * 16 + nn) * FD + n0 + c4]);
        }
        CP_COMMIT();
    }

    int cs = 0;
    for (int c = 0; c < 32; c++) {
        CP_WAIT1();
        __syncthreads();
        if (c + 2 < 32) {
            int es = cs + 2; if (es >= 3) es -= 3;
            int c0 = (c + 2) * 16;
            unsigned* Ad = Ap + es * KV_A;
            unsigned* Bd = Bp + es * KV_B;
            cpa16(&Ad[an * 72 + ak4], &K[(size_t)(c0 + an) * DK + m0 + ak4]);
#pragma unroll
            for (int it = 0; it < 4; it++) {
                int e = it * 256 + tid;
                int nn = e >> 6, c4 = (e & 63) * 4;
                cpa16(&Bd[nn * 264 + c4], &V[(size_t)(c0 + nn) * FD + n0 + c4]);
            }
        }
        CP_COMMIT();
        const unsigned* As = Ap + cs * KV_A;
        const unsigned* Bs = Bp + cs * KV_B;
#pragma unroll
        for (int k8 = 0; k8 < 2; k8++) {
            unsigned a[2][4];
            int ra0 = (k8 * 8 + qc) * 72;
            int ra1 = (k8 * 8 + qc + 4) * 72;
#pragma unroll
            for (int mi = 0; mi < 2; mi++) {
                int mb = wm * 32 + mi * 16 + qr;
                a[mi][0] = As[ra0 + mb];
                a[mi][1] = As[ra0 + mb + 8];
                a[mi][2] = As[ra1 + mb];
                a[mi][3] = As[ra1 + mb + 8];
            }
            int rb0 = (k8 * 8 + qc) * 264 + wn * 64 + qr;
            int rb1 = (k8 * 8 + qc + 4) * 264 + wn * 64 + qr;
#pragma unroll
            for (int j = 0; j < 8; j++) {
                unsigned b[2] = {Bs[rb0 + j * 8], Bs[rb1 + j * 8]};
                mma_tf32(acc[0][j], a[0], b);
                mma_tf32(acc[1][j], a[1], b);
            }
        }
        cs = (cs == 2) ? 0 : cs + 1;
    }
#pragma unroll
    for (int mi = 0; mi < 2; mi++) {
#pragma unroll
        for (int half = 0; half < 2; half++) {
            int m = m0 + wm * 32 + mi * 16 + half * 8 + qr;
#pragma unroll
            for (int j = 0; j < 8; j++) {
#pragma unroll
                for (int cc = 0; cc < 2; cc++) {
                    int d = n0 + wn * 64 + j * 8 + qc * 2 + cc;
                    C[(size_t)m * FD + d] = acc[mi][j][half * 2 + cc];
                }
            }
        }
    }
}

// ------ kernel 4: out = x + (q@kvl)/zl + (q@kvr)/zr, dual-B tf32 mma, 3-stage ------
#define AO_A 1280   // 64*20
#define AO_B 2176   // 16*136
__global__ __launch_bounds__(256, 2) void attnout_mma_kernel(const float* __restrict__ x) {
    extern __shared__ unsigned asm_[];
    unsigned* Ap = asm_;                        // 3 * AO_A
    unsigned* Blp = asm_ + 3 * AO_A;            // 3 * AO_B
    unsigned* Brp = asm_ + 3 * AO_A + 3 * AO_B; // 3 * AO_B

    int sample = blockIdx.z;
    const float* Q = g_q + (size_t)sample * INC * DK;
    const float* KVL = g_kvl + (size_t)sample * DK * FD;
    const float* KVR = g_kvr + (size_t)sample * DK * FD;
    const float* Zl = g_z + (size_t)sample * INC;
    const float* Zr = g_z + (size_t)(NS + sample) * INC;
    const float* X = x + (size_t)(sample + 1) * INC * FD;
    float* C = g_mid + (size_t)sample * INC * FD;

    int m0 = blockIdx.x * 64;
    int n0 = blockIdx.y * 128;
    int tid = threadIdx.x;
    int warp = tid >> 5, lane = tid & 31;
    int wm = warp & 1, wn = warp >> 1;
    int qr = lane >> 2, qc = lane & 3;

    int am = tid >> 2, ak4 = (tid & 3) * 4;

    float accl[2][4][4] = {}, accr[2][4][4] = {};

    // prologue: chunks 0,1
#pragma unroll
    for (int s = 0; s < 2; s++) {
        unsigned* Ad = Ap + s * AO_A;
        unsigned* Bld = Blp + s * AO_B;
        unsigned* Brd = Brp + s * AO_B;
        cpa16(&Ad[am * 20 + ak4], &Q[(size_t)(m0 + am) * DK + s * 16 + ak4]);
#pragma unroll
        for (int it = 0; it < 2; it++) {
            int e = it * 256 + tid;
            int kk = e >> 5, c4 = (e & 31) * 4;
            cpa16(&Bld[kk * 136 + c4], &KVL[(size_t)(s * 16 + kk) * FD + n0 + c4]);
            cpa16(&Brd[kk * 136 + c4], &KVR[(size_t)(s * 16 + kk) * FD + n0 + c4]);
        }
        CP_COMMIT();
    }

    int cs = 0;
    for (int c = 0; c < 8; c++) {
        CP_WAIT1();
        __syncthreads();
        if (c + 2 < 8) {
            int es = cs + 2; if (es >= 3) es -= 3;
            int k0 = (c + 2) * 16;
            unsigned* Ad = Ap + es * AO_A;
            unsigned* Bld = Blp + es * AO_B;
            unsigned* Brd = Brp + es * AO_B;
            cpa16(&Ad[am * 20 + ak4], &Q[(size_t)(m0 + am) * DK + k0 + ak4]);
#pragma unroll
            for (int it = 0; it < 2; it++) {
                int e = it * 256 + tid;
                int kk = e >> 5, c4 = (e & 31) * 4;
                cpa16(&Bld[kk * 136 + c4], &KVL[(size_t)(k0 + kk) * FD + n0 + c4]);
                cpa16(&Brd[kk * 136 + c4], &KVR[(size_t)(k0 + kk) * FD + n0 + c4]);
            }
        }
        CP_COMMIT();
        const unsigned* As = Ap + cs * AO_A;
        const unsigned* Bl = Blp + cs * AO_B;
        const unsigned* Br = Brp + cs * AO_B;
#pragma unroll
        for (int k8 = 0; k8 < 2; k8++) {
            unsigned a[2][4];
            int kb = k8 * 8 + qc;
#pragma unroll
            for (int mi = 0; mi < 2; mi++) {
                int mb = wm * 32 + mi * 16 + qr;
                a[mi][0] = As[mb * 20 + kb];
                a[mi][1] = As[(mb + 8) * 20 + kb];
                a[mi][2] = As[mb * 20 + kb + 4];
                a[mi][3] = As[(mb + 8) * 20 + kb + 4];
            }
            int rb0 = (k8 * 8 + qc) * 136 + wn * 32 + qr;
            int rb1 = (k8 * 8 + qc + 4) * 136 + wn * 32 + qr;
#pragma unroll
            for (int j = 0; j < 4; j++) {
                unsigned bl[2] = {Bl[rb0 + j * 8], Bl[rb1 + j * 8]};
                unsigned br[2] = {Br[rb0 + j * 8], Br[rb1 + j * 8]};
                mma_tf32(accl[0][j], a[0], bl);
                mma_tf32(accl[1][j], a[1], bl);
                mma_tf32(accr[0][j], a[0], br);
                mma_tf32(accr[1][j], a[1], br);
            }
        }
        cs = (cs == 2) ? 0 : cs + 1;
    }
#pragma unroll
    for (int mi = 0; mi < 2; mi++) {
#pragma unroll
        for (int half = 0; half < 2; half++) {
            int m = m0 + wm * 32 + mi * 16 + half * 8 + qr;
            float zl = Zl[m], zr = Zr[m];
#pragma unroll
            for (int j = 0; j < 4; j++) {
#pragma unroll
                for (int cc = 0; cc < 2; cc++) {
                    int d = n0 + wn * 32 + j * 8 + qc * 2 + cc;
                    C[(size_t)m * FD + d] = X[(size_t)m * FD + d]
                        + accl[mi][j][half * 2 + cc] / zl
                        + accr[mi][j][half * 2 + cc] / zr;
                }
            }
        }
    }
}

// ------ kernel 5: ConvTranspose 2x2 s2 via tf32 mma + fused gate, 3-stage ------
// Also zeroes the BN accumulators (replaces the separate zero_kernel launch).
#define CT_A 1152   // 16*72
#define CT_B 4224   // 16*264
__global__ __launch_bounds__(256, 2) void convt_mma_kernel(
    const float* __restrict__ x, const float* __restrict__ upw,
    const float* __restrict__ upb, const float* __restrict__ s) {
    extern __shared__ unsigned csm[];
    unsigned* Ap = csm;               // 3 * CT_A
    unsigned* Bp = csm + 3 * CT_A;    // 3 * CT_B

    int n = blockIdx.z;
    const float* src = (n == 0) ? x
                     : (n == BB - 1) ? (x + (size_t)(BB - 1) * INC * FD)
                     : (g_mid + (size_t)(n - 1) * INC * FD);
    int m0 = blockIdx.x * 64;
    int n0 = blockIdx.y * 256;

    if (blockIdx.x == 0 && blockIdx.y == 0 && blockIdx.z == 0) {
        g_bnsum[threadIdx.x] = 0.f;
        g_bnsq[threadIdx.x] = 0.f;
    }

    int tid = threadIdx.x;
    int warp = tid >> 5, lane = tid & 31;
    int wm = warp & 1;
    int wn = warp >> 1;
    int qr = lane >> 2;
    int qc = lane & 3;

    int ac = tid >> 4, am4 = (tid & 15) * 4;

    float acc[2][8][4] = {};

    // prologue: chunks 0,1
#pragma unroll
    for (int st = 0; st < 2; st++) {
        unsigned* Ad = Ap + st * CT_A;
        unsigned* Bd = Bp + st * CT_B;
        cpa16(&Ad[ac * 72 + am4], &upw[(size_t)(st * 16 + ac) * 1024 + m0 + am4]);
#pragma unroll
        for (int it = 0; it < 4; it++) {
            int e = it * 256 + tid;
            int cc = e >> 6, c4 = (e & 63) * 4;
            cpa16(&Bd[cc * 264 + c4], &src[(size_t)(st * 16 + cc) * FD + n0 + c4]);
        }
        CP_COMMIT();
    }

    int cs = 0;
    for (int c = 0; c < 32; c++) {
        CP_WAIT1();
        __syncthreads();
        if (c + 2 < 32) {
            int es = cs + 2; if (es >= 3) es -= 3;
            int c0 = (c + 2) * 16;
            unsigned* Ad = Ap + es * CT_A;
            unsigned* Bd = Bp + es * CT_B;
            cpa16(&Ad[ac * 72 + am4], &upw[(size_t)(c0 + ac) * 1024 + m0 + am4]);
#pragma unroll
            for (int it = 0; it < 4; it++) {
                int e = it * 256 + tid;
                int cc = e >> 6, c4 = (e & 63) * 4;
                cpa16(&Bd[cc * 264 + c4], &src[(size_t)(c0 + cc) * FD + n0 + c4]);
            }
        }
        CP_COMMIT();
        const unsigned* As = Ap + cs * CT_A;
        const unsigned* Bs = Bp + cs * CT_B;
#pragma unroll
        for (int k8 = 0; k8 < 2; k8++) {
            unsigned a[2][4];
            int ra0 = (k8 * 8 + qc) * 72;
            int ra1 = (k8 * 8 + qc + 4) * 72;
#pragma unroll
            for (int mi = 0; mi < 2; mi++) {
                int ocb = wm * 32 + mi * 16 + qr;
                a[mi][0] = As[ra0 + ocb];
                a[mi][1] = As[ra0 + ocb + 8];
                a[mi][2] = As[ra1 + ocb];
                a[mi][3] = As[ra1 + ocb + 8];
            }
            int rb0 = (k8 * 8 + qc) * 264 + wn * 64 + qr;
            int rb1 = (k8 * 8 + qc + 4) * 264 + wn * 64 + qr;
#pragma unroll
            for (int j = 0; j < 8; j++) {
                unsigned b[2] = {Bs[rb0 + j * 8], Bs[rb1 + j * 8]};
                mma_tf32(acc[0][j], a[0], b);
                mma_tf32(acc[1][j], a[1], b);
            }
        }
        cs = (cs == 2) ? 0 : cs + 1;
    }
    // epilogue: bias + skip + relu + sigmoid, scatter to g_gate
#pragma unroll
    for (int mi = 0; mi < 2; mi++) {
#pragma unroll
        for (int half = 0; half < 2; half++) {
            int row = m0 + wm * 32 + mi * 16 + half * 8 + qr;
            int o = row >> 2, ab = row & 3, av = ab >> 1, bq = ab & 1;
            float bias = upb[o];
#pragma unroll
            for (int j = 0; j < 8; j++) {
#pragma unroll
                for (int cc = 0; cc < 2; cc++) {
                    int col = n0 + wn * 64 + j * 8 + qc * 2 + cc;
                    int isp = col >> 5, jsp = col & 31;
                    int oy = 2 * isp + av, ox = 2 * jsp + bq;
                    size_t gi = (((size_t)n * OUTC + o) * OH + oy) * OW + ox;
                    float v = acc[mi][j][half * 2 + cc] + bias + s[gi];
                    v = v > 0.f ? v : 0.f;
                    g_gate[gi] = 1.f / (1.f + expf(-v));
                }
            }
        }
    }
}

// ---------------- kernel 6: conv3x3 via tf32 mma, cp.async pipeline (unchanged) ----------------
#define PS 744
#define INW (8 * PS)
#define WW_ 4864
__global__ __launch_bounds__(256) void conv_mma_kernel(
    const float* __restrict__ sskip, const float* __restrict__ cw,
    const float* __restrict__ cb) {
    extern __shared__ unsigned dyns[];
    unsigned* inb = dyns;
    unsigned* wb = dyns + 2 * INW;
    float* rs = (float*)(dyns + 2 * INW + 2 * WW_);
    float* rq = rs + 64;

    int n = blockIdx.z;
    int oc0 = blockIdx.y * 64;
    int y0 = blockIdx.x * 8;

    int tid = threadIdx.x;
    int warp = tid >> 5, lane = tid & 31;
    int wn = warp;
    int qr = lane >> 2;
    int qc = lane & 3;

    for (int e = tid; e < 320; e += 256) {
        int bsel = e >= 160;
        int r2 = e - bsel * 160;
        int r = r2 >> 1;
        int icc = r / 10, yy = r - icc * 10;
        inb[bsel * INW + icc * PS + yy * 72 + ((r2 & 1) ? 68 : 3)] = 0u;
    }
    if (tid < 64) { rs[tid] = 0.f; rq[tid] = 0.f; }

    float acc[4][8][4] = {};

    int seg = (tid & 15) * 4;
    int rbase = tid >> 4;

#pragma unroll
    for (int i = 0; i < 5; i++) {
        int r = rbase + 16 * i;
        int icc = r / 10, yy = r - icc * 10;
        int gy = y0 + yy - 1;
        int ic = icc;
        int gyc = gy < 0 ? 0 : (gy > OH - 1 ? OH - 1 : gy);
        const float* srcp = (ic < OUTC)
            ? &g_gate[(((size_t)n * OUTC + ic) * OH + gyc) * OW + seg]
            : &sskip[(((size_t)n * OUTC + (ic - OUTC)) * OH + gyc) * OW + seg];
        int sz = ((unsigned)gy < (unsigned)OH) ? 16 : 0;
        cpa16z(&inb[icc * PS + yy * 72 + 4 + seg], srcp, sz);
    }
#pragma unroll
    for (int i = 0; i < 5; i++) {
        int e = tid + 256 * i;
        if (e < 1152) {
            int oc = e / 18, f = e - oc * 18;
            cpa16(&wb[oc * 76 + f * 4], &cw[(size_t)(oc0 + oc) * (2 * OUTC * 9) + f * 4]);
        }
    }
    CP_COMMIT();

    int pi = 0;
    for (int c = 0; c < 64; c++) {
        CP_WAIT0();
        __syncthreads();
        if (c < 63) {
            int ic0 = (c + 1) * 8;
            unsigned* ind = inb + (pi ? 0 : INW);
            unsigned* wd = wb + (pi ? 0 : WW_);
#pragma unroll
            for (int i = 0; i < 5; i++) {
                int r = rbase + 16 * i;
                int icc = r / 10, yy = r - icc * 10;
                int gy = y0 + yy - 1;
                int ic = ic0 + icc;
                int gyc = gy < 0 ? 0 : (gy > OH - 1 ? OH - 1 : gy);
                const float* srcp = (ic < OUTC)
                    ? &g_gate[(((size_t)n * OUTC + ic) * OH + gyc) * OW + seg]
                    : &sskip[(((size_t)n * OUTC + (ic - OUTC)) * OH + gyc) * OW + seg];
                int sz = ((unsigned)gy < (unsigned)OH) ? 16 : 0;
                cpa16z(&ind[icc * PS + yy * 72 + 4 + seg], srcp, sz);
            }
#pragma unroll
            for (int i = 0; i < 5; i++) {
                int e = tid + 256 * i;
                if (e < 1152) {
                    int oc = e / 18, f = e - oc * 18;
                    cpa16(&wd[oc * 76 + f * 4], &cw[(size_t)(oc0 + oc) * (2 * OUTC * 9) + ic0 * 9 + f * 4]);
                }
            }
            CP_COMMIT();
        }
        const unsigned* in_s = inb + (pi ? INW : 0);
        const unsigned* w_s = wb + (pi ? WW_ : 0);
#pragma unroll
        for (int ky = 0; ky < 3; ky++) {
            int rowoff = (wn + ky) * 72 + 3;
#pragma unroll
            for (int kx = 0; kx < 3; kx++) {
                int pos = ky * 3 + kx;
                unsigned a[4][4];
#pragma unroll
                for (int mi = 0; mi < 4; mi++) {
                    int ocb = mi * 16 + qr;
                    a[mi][0] = w_s[ocb * 76 + qc * 9 + pos];
                    a[mi][1] = w_s[(ocb + 8) * 76 + qc * 9 + pos];
                    a[mi][2] = w_s[ocb * 76 + (qc + 4) * 9 + pos];
                    a[mi][3] = w_s[(ocb + 8) * 76 + (qc + 4) * 9 + pos];
                }
#pragma unroll
                for (int j = 0; j < 8; j++) {
                    int col = j * 8 + qr + kx;
                    unsigned b[2] = {in_s[qc * PS + rowoff + col],
                                     in_s[(qc + 4) * PS + rowoff + col]};
                    mma_tf32(acc[0][j], a[0], b);
                    mma_tf32(acc[1][j], a[1], b);
                    mma_tf32(acc[2][j], a[2], b);
                    mma_tf32(acc[3][j], a[3], b);
                }
            }
        }
        pi ^= 1;
    }

    int row = y0 + wn;
#pragma unroll
    for (int mi = 0; mi < 4; mi++) {
#pragma unroll
        for (int half = 0; half < 2; half++) {
            int ocl = mi * 16 + half * 8 + qr;
            int oc = oc0 + ocl;
            float bias = cb[oc];
            float s0 = 0.f, s1 = 0.f;
#pragma unroll
            for (int j = 0; j < 8; j++) {
#pragma unroll
                for (int cc = 0; cc < 2; cc++) {
                    float v = acc[mi][j][half * 2 + cc] + bias;
                    int col = j * 8 + qc * 2 + cc;
                    g_y[(((size_t)n * OUTC + oc) * OH + row) * OW + col] = v;
                    s0 += v;
                    s1 += v * v;
                }
            }
            s0 += __shfl_xor_sync(0xffffffffu, s0, 1);
            s0 += __shfl_xor_sync(0xffffffffu, s0, 2);
            s1 += __shfl_xor_sync(0xffffffffu, s1, 1);
            s1 += __shfl_xor_sync(0xffffffffu, s1, 2);
            if (qc == 0) {
                atomicAdd(&rs[ocl], s0);
                atomicAdd(&rq[ocl], s1);
            }
        }
    }
    __syncthreads();
    if (tid < 64) {
        atomicAdd(&g_bnsum[oc0 + tid], rs[tid]);
        atomicAdd(&g_bnsq[oc0 + tid], rq[tid]);
    }
}

// ---------------- small kernels ----------------
__global__ void bnstats_kernel(const float* __restrict__ bn_g, const float* __restrict__ bn_b) {
    int c = threadIdx.x;
    float cnt = (float)(BB * OH * OW);
    float mean = g_bnsum[c] / cnt;
    float var = g_bnsq[c] / cnt - mean * mean;
    float inv = rsqrtf(var + 1e-5f);
    float sc = bn_g[c] * inv;
    g_bnscale[c] = sc;
    g_bnshift[c] = bn_b[c] - mean * sc;
}

__global__ void bnorm_kernel(float* __restrict__ out) {
    int i4 = blockIdx.x * blockDim.x + threadIdx.x;
    const int total4 = BB * OUTC * OH * OW / 4;
    if (i4 >= total4) return;
    int base = i4 * 4;
    int oc = (base >> 12) & (OUTC - 1);
    float sc = g_bnscale[oc], sh = g_bnshift[oc];
    float4 v = *(const float4*)&g_y[base];
    float4 r;
    r.x = fmaxf(v.x * sc + sh, 0.f);
    r.y = fmaxf(v.y * sc + sh, 0.f);
    r.z = fmaxf(v.z * sc + sh, 0.f);
    r.w = fmaxf(v.w * sc + sh, 0.f);
    *(float4*)&out[base] = r;
}

// ---------------- launcher ----------------
extern "C" void kernel_launch(void* const* d_in, const int* in_sizes, int n_in,
                              void* d_out, int out_size) {
    const float* x    = (const float*)d_in[0];
    const float* s    = (const float*)d_in[1];
    const float* up_w = (const float*)d_in[2];
    const float* up_b = (const float*)d_in[3];
    const float* wq   = (const float*)d_in[4];
    const float* wkl  = (const float*)d_in[5];
    const float* wkr  = (const float*)d_in[6];
    const float* c1_w = (const float*)d_in[7];
    const float* c1_b = (const float*)d_in[8];
    const float* bn_g = (const float*)d_in[9];
    const float* bn_b = (const float*)d_in[10];
    float* out = (float*)d_out;

    const int conv_smem = (2 * INW + 2 * WW_) * 4 + 128 * 4;      // 87040 B
    const int proj_smem = (4 * PJ_A + 4 * PJ_B) * 4;              // 55296 B
    const int kv_smem   = (3 * KV_A + 3 * KV_B) * 4;              // 64512 B
    const int ao_smem   = (3 * AO_A + 6 * AO_B) * 4;              // 67584 B
    const int cvt_smem  = (3 * CT_A + 3 * CT_B) * 4;              // 64512 B
    cudaFuncSetAttribute(conv_mma_kernel,
                         cudaFuncAttributeMaxDynamicSharedMemorySize, conv_smem);
    cudaFuncSetAttribute(proj_mma_kernel,
                         cudaFuncAttributeMaxDynamicSharedMemorySize, proj_smem);
    cudaFuncSetAttribute(kv_mma_kernel,
                         cudaFuncAttributeMaxDynamicSharedMemorySize, kv_smem);
    cudaFuncSetAttribute(attnout_mma_kernel,
                         cudaFuncAttributeMaxDynamicSharedMemorySize, ao_smem);
    cudaFuncSetAttribute(convt_mma_kernel,
                         cudaFuncAttributeMaxDynamicSharedMemorySize, cvt_smem);

    proj_mma_kernel<<<dim3(8, 1, NS * 3), 256, proj_smem>>>(x, wq, wkl, wkr);
    sumz_kernel<<<dim3(NS, 2), 128>>>();
    kv_mma_kernel<<<dim3(2, 4, NS * 2), 256, kv_smem>>>(x);
    attnout_mma_kernel<<<dim3(8, 8, NS), 256, ao_smem>>>(x);
    convt_mma_kernel<<<dim3(16, 4, BB), 256, cvt_smem>>>(x, up_w, up_b, s);
    conv_mma_kernel<<<dim3(8, 4, BB), 256, conv_smem>>>(s, c1_w, c1_b);
    bnstats_kernel<<<1, OUTC>>>(bn_g, bn_b);
    int total4 = BB * OUTC * OH * OW / 4;
    bnorm_kernel<<<(total4 + 255) / 256, 256>>>(out);
}

// round 16
// speedup vs baseline: 1.1083x; 1.0036x over previous
#include <cuda_runtime.h>
#include <math.h>

#define BB 16
#define INC 512
#define OUTC 256
#define HH 32
#define WW 32
#define FD 1024
#define DK 128
#define NS 14          // interior samples (B-2)
#define OH 64
#define OW 64

// ---------------- scratch (static device memory; no allocation) ----------------
__device__ float g_mid[NS * INC * FD];
__device__ float g_q[NS * INC * DK];
__device__ float g_kl[NS * INC * DK];
__device__ float g_kr[NS * INC * DK];
__device__ float g_kvl[NS * DK * FD];
__device__ float g_kvr[NS * DK * FD];
__device__ float g_z[2 * NS * INC];
__device__ float g_gate[BB * OUTC * OH * OW];
__device__ float g_y[BB * OUTC * OH * OW];
__device__ float g_bnsum[OUTC];
__device__ float g_bnsq[OUTC];
__device__ float g_bnscale[OUTC];
__device__ float g_bnshift[OUTC];

// ---------------- tf32 mma helpers ----------------
// Raw fp32 bit patterns are fed to the tf32 MMA (HW truncates low mantissa).
__device__ __forceinline__ void mma_tf32(float (&d)[4], const unsigned (&a)[4], const unsigned (&b)[2]) {
    asm("mma.sync.aligned.m16n8k8.row.col.f32.tf32.tf32.f32 "
        "{%0,%1,%2,%3}, {%4,%5,%6,%7}, {%8,%9}, {%0,%1,%2,%3};"
        : "+f"(d[0]), "+f"(d[1]), "+f"(d[2]), "+f"(d[3])
        : "r"(a[0]), "r"(a[1]), "r"(a[2]), "r"(a[3]), "r"(b[0]), "r"(b[1]));
}

__device__ __forceinline__ void cpa16(void* d, const void* s) {
    unsigned sa = (unsigned)__cvta_generic_to_shared(d);
    asm volatile("cp.async.cg.shared.global [%0], [%1], 16;" :: "r"(sa), "l"(s));
}
__device__ __forceinline__ void cpa16z(void* d, const void* s, int sz) {
    unsigned sa = (unsigned)__cvta_generic_to_shared(d);
    asm volatile("cp.async.cg.shared.global [%0], [%1], 16, %2;" :: "r"(sa), "l"(s), "r"(sz));
}
#define CP_COMMIT() asm volatile("cp.async.commit_group;")
#define CP_WAIT0()  asm volatile("cp.async.wait_group 0;")
#define CP_WAIT1()  asm volatile("cp.async.wait_group 1;")
#define CP_WAIT2()  asm volatile("cp.async.wait_group 2;")

// ---------------- kernel 1: projections q/kl/kr = phi(A @ W), 4-stage pipeline ----------------
#define PJ_A 1280   // 64*20
#define PJ_B 2176   // 16*136
__global__ __launch_bounds__(256, 2) void proj_mma_kernel(
    const float* __restrict__ x, const float* __restrict__ wq,
    const float* __restrict__ wkl, const float* __restrict__ wkr) {
    extern __shared__ unsigned psm[];
    unsigned* Ap = psm;               // 4 * PJ_A
    unsigned* Bp = psm + 4 * PJ_A;    // 4 * PJ_B

    int zi = blockIdx.z;
    int sample = zi / 3, p = zi % 3;
    const float* A;
    const float* Wm;
    float* C;
    if (p == 0)      { A = x + (size_t)(sample + 1) * INC * FD; Wm = wq;  C = g_q  + (size_t)sample * INC * DK; }
    else if (p == 1) { A = x + (size_t)(sample + 0) * INC * FD; Wm = wkl; C = g_kl + (size_t)sample * INC * DK; }
    else             { A = x + (size_t)(sample + 2) * INC * FD; Wm = wkr; C = g_kr + (size_t)sample * INC * DK; }

    int m0 = blockIdx.x * 64;
    int tid = threadIdx.x;
    int warp = tid >> 5, lane = tid & 31;
    int wm = warp & 3;
    int wn = warp >> 2;
    int qr = lane >> 2, qc = lane & 3;

    int am = tid >> 2, ak4 = (tid & 3) * 4;

    float acc[8][4] = {};

    // prologue: issue chunks 0..2
#pragma unroll
    for (int s = 0; s < 3; s++) {
        unsigned* Ad = Ap + s * PJ_A;
        unsigned* Bd = Bp + s * PJ_B;
        cpa16(&Ad[am * 20 + ak4], &A[(size_t)(m0 + am) * FD + s * 16 + ak4]);
#pragma unroll
        for (int it = 0; it < 2; it++) {
            int e = it * 256 + tid;
            int kk = e >> 5, c4 = (e & 31) * 4;
            cpa16(&Bd[kk * 136 + c4], &Wm[(size_t)(s * 16 + kk) * DK + c4]);
        }
        CP_COMMIT();
    }

    int cs = 0;
    for (int c = 0; c < 64; c++) {
        CP_WAIT2();
        __syncthreads();
        if (c + 3 < 64) {
            int es = cs + 3; if (es >= 4) es -= 4;
            int k0 = (c + 3) * 16;
            unsigned* Ad = Ap + es * PJ_A;
            unsigned* Bd = Bp + es * PJ_B;
            cpa16(&Ad[am * 20 + ak4], &A[(size_t)(m0 + am) * FD + k0 + ak4]);
#pragma unroll
            for (int it = 0; it < 2; it++) {
                int e = it * 256 + tid;
                int kk = e >> 5, c4 = (e & 31) * 4;
                cpa16(&Bd[kk * 136 + c4], &Wm[(size_t)(k0 + kk) * DK + c4]);
            }
        }
        CP_COMMIT();
        const unsigned* As = Ap + cs * PJ_A;
        const unsigned* Bs = Bp + cs * PJ_B;
#pragma unroll
        for (int k8 = 0; k8 < 2; k8++) {
            unsigned a[4];
            int mb = wm * 16 + qr;
            int kb = k8 * 8 + qc;
            a[0] = As[mb * 20 + kb];
            a[1] = As[(mb + 8) * 20 + kb];
            a[2] = As[mb * 20 + kb + 4];
            a[3] = As[(mb + 8) * 20 + kb + 4];
            int rb0 = (k8 * 8 + qc) * 136 + wn * 64 + qr;
            int rb1 = (k8 * 8 + qc + 4) * 136 + wn * 64 + qr;
#pragma unroll
            for (int j = 0; j < 8; j++) {
                unsigned b[2] = {Bs[rb0 + j * 8], Bs[rb1 + j * 8]};
                mma_tf32(acc[j], a, b);
            }
        }
        cs = (cs == 3) ? 0 : cs + 1;
    }
    // epilogue: phi = elu + 1
#pragma unroll
    for (int half = 0; half < 2; half++) {
        int m = m0 + wm * 16 + half * 8 + qr;
#pragma unroll
        for (int j = 0; j < 8; j++) {
#pragma unroll
            for (int cc = 0; cc < 2; cc++) {
                int ncol = wn * 64 + j * 8 + qc * 2 + cc;
                float v = acc[j][half * 2 + cc];
                C[(size_t)m * DK + ncol] = (v > 0.f) ? (v + 1.f) : expf(v);
            }
        }
    }
}

// ---------------- kernel 2: column sums + z = q @ ksum + 1e-6 ----------------
__global__ void sumz_kernel() {
    int sample = blockIdx.x;
    int side = blockIdx.y;
    const float* K = (side == 0 ? g_kl : g_kr) + (size_t)sample * INC * DK;
    const float* Q = g_q + (size_t)sample * INC * DK;
    __shared__ float ssum[DK];
    int t = threadIdx.x;
    float s = 0.f;
    for (int n = 0; n < INC; n++) s += K[n * DK + t];
    ssum[t] = s;
    __syncthreads();
    float* Z = g_z + (size_t)(side * NS + sample) * INC;
    for (int rr = 0; rr < 4; rr++) {
        int row = rr * 128 + t;
        float d = 0.f;
        for (int k = 0; k < DK; k++) d += Q[row * DK + k] * ssum[k];
        Z[row] = d + 1e-6f;
    }
}

// ---------------- kernel 3: kv[k][d] = sum_n K[n][k] * V[n][d], 3-stage pipeline ----------------
#define KV_A 1152   // 16*72
#define KV_B 4224   // 16*264
__global__ __launch_bounds__(256, 2) void kv_mma_kernel(const float* __restrict__ x) {
    extern __shared__ unsigned ksm[];
    unsigned* Ap = ksm;               // 3 * KV_A
    unsigned* Bp = ksm + 3 * KV_A;    // 3 * KV_B

    int zi = blockIdx.z;
    int sample = zi >> 1, side = zi & 1;
    const float* K = (side == 0 ? g_kl : g_kr) + (size_t)sample * INC * DK;
    const float* V = x + (size_t)(sample + (side == 0 ? 0 : 2)) * INC * FD;
    float* C = (side == 0 ? g_kvl : g_kvr) + (size_t)sample * DK * FD;

    int m0 = blockIdx.x * 64;
    int n0 = blockIdx.y * 256;
    int tid = threadIdx.x;
    int warp = tid >> 5, lane = tid & 31;
    int wm = warp & 1, wn = warp >> 1;
    int qr = lane >> 2, qc = lane & 3;

    int an = tid >> 4, ak4 = (tid & 15) * 4;

    float acc[2][8][4] = {};

    // prologue: chunks 0,1
#pragma unroll
    for (int s = 0; s < 2; s++) {
        unsigned* Ad = Ap + s * KV_A;
        unsigned* Bd = Bp + s * KV_B;
        cpa16(&Ad[an * 72 + ak4], &K[(size_t)(s * 16 + an) * DK + m0 + ak4]);
#pragma unroll
        for (int it = 0; it < 4; it++) {
            int e = it * 256 + tid;
            int nn = e >> 6, c4 = (e & 63) * 4;
            cpa16(&Bd[nn * 264 + c4], &V[(size_t)(s * 16 + nn) * FD + n0 + c4]);
        }
        CP_COMMIT();
    }

    int cs = 0;
    for (int c = 0; c < 32; c++) {
        CP_WAIT1();
        __syncthreads();
        if (c + 2 < 32) {
            int es = cs + 2; if (es >= 3) es -= 3;
            int c0 = (c + 2) * 16;
            unsigned* Ad = Ap + es * KV_A;
            unsigned* Bd = Bp + es * KV_B;
            cpa16(&Ad[an * 72 + ak4], &K[(size_t)(c0 + an) * DK + m0 + ak4]);
#pragma unroll
            for (int it = 0; it < 4; it++) {
                int e = it * 256 + tid;
                int nn = e >> 6, c4 = (e & 63) * 4;
                cpa16(&Bd[nn * 264 + c4], &V[(size_t)(c0 + nn) * FD + n0 + c4]);
            }
        }
        CP_COMMIT();
        const unsigned* As = Ap + cs * KV_A;
        const unsigned* Bs = Bp + cs * KV_B;
#pragma unroll
        for (int k8 = 0; k8 < 2; k8++) {
            unsigned a[2][4];
            int ra0 = (k8 * 8 + qc) * 72;
            int ra1 = (k8 * 8 + qc + 4) * 72;
#pragma unroll
            for (int mi = 0; mi < 2; mi++) {
                int mb = wm * 32 + mi * 16 + qr;
                a[mi][0] = As[ra0 + mb];
                a[mi][1] = As[ra0 + mb + 8];
                a[mi][2] = As[ra1 + mb];
                a[mi][3] = As[ra1 + mb + 8];
            }
            int rb0 = (k8 * 8 + qc) * 264 + wn * 64 + qr;
            int rb1 = (k8 * 8 + qc + 4) * 264 + wn * 64 + qr;
#pragma unroll
            for (int j = 0; j < 8; j++) {
                unsigned b[2] = {Bs[rb0 + j * 8], Bs[rb1 + j * 8]};
                mma_tf32(acc[0][j], a[0], b);
                mma_tf32(acc[1][j], a[1], b);
            }
        }
        cs = (cs == 2) ? 0 : cs + 1;
    }
#pragma unroll
    for (int mi = 0; mi < 2; mi++) {
#pragma unroll
        for (int half = 0; half < 2; half++) {
            int m = m0 + wm * 32 + mi * 16 + half * 8 + qr;
#pragma unroll
            for (int j = 0; j < 8; j++) {
#pragma unroll
                for (int cc = 0; cc < 2; cc++) {
                    int d = n0 + wn * 64 + j * 8 + qc * 2 + cc;
                    C[(size_t)m * FD + d] = acc[mi][j][half * 2 + cc];
                }
            }
        }
    }
}

// ------ kernel 4: out = x + (q@kvl)/zl + (q@kvr)/zr, dual-B tf32 mma, 3-stage ------
#define AO_A 1280   // 64*20
#define AO_B 2176   // 16*136
__global__ __launch_bounds__(256, 2) void attnout_mma_kernel(const float* __restrict__ x) {
    extern __shared__ unsigned asm_[];
    unsigned* Ap = asm_;                        // 3 * AO_A
    unsigned* Blp = asm_ + 3 * AO_A;            // 3 * AO_B
    unsigned* Brp = asm_ + 3 * AO_A + 3 * AO_B; // 3 * AO_B

    int sample = blockIdx.z;
    const float* Q = g_q + (size_t)sample * INC * DK;
    const float* KVL = g_kvl + (size_t)sample * DK * FD;
    const float* KVR = g_kvr + (size_t)sample * DK * FD;
    const float* Zl = g_z + (size_t)sample * INC;
    const float* Zr = g_z + (size_t)(NS + sample) * INC;
    const float* X = x + (size_t)(sample + 1) * INC * FD;
    float* C = g_mid + (size_t)sample * INC * FD;

    int m0 = blockIdx.x * 64;
    int n0 = blockIdx.y * 128;
    int tid = threadIdx.x;
    int warp = tid >> 5, lane = tid & 31;
    int wm = warp & 1, wn = warp >> 1;
    int qr = lane >> 2, qc = lane & 3;

    int am = tid >> 2, ak4 = (tid & 3) * 4;

    float accl[2][4][4] = {}, accr[2][4][4] = {};

    // prologue: chunks 0,1
#pragma unroll
    for (int s = 0; s < 2; s++) {
        unsigned* Ad = Ap + s * AO_A;
        unsigned* Bld = Blp + s * AO_B;
        unsigned* Brd = Brp + s * AO_B;
        cpa16(&Ad[am * 20 + ak4], &Q[(size_t)(m0 + am) * DK + s * 16 + ak4]);
#pragma unroll
        for (int it = 0; it < 2; it++) {
            int e = it * 256 + tid;
            int kk = e >> 5, c4 = (e & 31) * 4;
            cpa16(&Bld[kk * 136 + c4], &KVL[(size_t)(s * 16 + kk) * FD + n0 + c4]);
            cpa16(&Brd[kk * 136 + c4], &KVR[(size_t)(s * 16 + kk) * FD + n0 + c4]);
        }
        CP_COMMIT();
    }

    int cs = 0;
    for (int c = 0; c < 8; c++) {
        CP_WAIT1();
        __syncthreads();
        if (c + 2 < 8) {
            int es = cs + 2; if (es >= 3) es -= 3;
            int k0 = (c + 2) * 16;
            unsigned* Ad = Ap + es * AO_A;
            unsigned* Bld = Blp + es * AO_B;
            unsigned* Brd = Brp + es * AO_B;
            cpa16(&Ad[am * 20 + ak4], &Q[(size_t)(m0 + am) * DK + k0 + ak4]);
#pragma unroll
            for (int it = 0; it < 2; it++) {
                int e = it * 256 + tid;
                int kk = e >> 5, c4 = (e & 31) * 4;
                cpa16(&Bld[kk * 136 + c4], &KVL[(size_t)(k0 + kk) * FD + n0 + c4]);
                cpa16(&Brd[kk * 136 + c4], &KVR[(size_t)(k0 + kk) * FD + n0 + c4]);
            }
        }
        CP_COMMIT();
        const unsigned* As = Ap + cs * AO_A;
        const unsigned* Bl = Blp + cs * AO_B;
        const unsigned* Br = Brp + cs * AO_B;
#pragma unroll
        for (int k8 = 0; k8 < 2; k8++) {
            unsigned a[2][4];
            int kb = k8 * 8 + qc;
#pragma unroll
            for (int mi = 0; mi < 2; mi++) {
                int mb = wm * 32 + mi * 16 + qr;
                a[mi][0] = As[mb * 20 + kb];
                a[mi][1] = As[(mb + 8) * 20 + kb];
                a[mi][2] = As[mb * 20 + kb + 4];
                a[mi][3] = As[(mb + 8) * 20 + kb + 4];
            }
            int rb0 = (k8 * 8 + qc) * 136 + wn * 32 + qr;
            int rb1 = (k8 * 8 + qc + 4) * 136 + wn * 32 + qr;
#pragma unroll
            for (int j = 0; j < 4; j++) {
                unsigned bl[2] = {Bl[rb0 + j * 8], Bl[rb1 + j * 8]};
                unsigned br[2] = {Br[rb0 + j * 8], Br[rb1 + j * 8]};
                mma_tf32(accl[0][j], a[0], bl);
                mma_tf32(accl[1][j], a[1], bl);
                mma_tf32(accr[0][j], a[0], br);
                mma_tf32(accr[1][j], a[1], br);
            }
        }
        cs = (cs == 2) ? 0 : cs + 1;
    }
#pragma unroll
    for (int mi = 0; mi < 2; mi++) {
#pragma unroll
        for (int half = 0; half < 2; half++) {
            int m = m0 + wm * 32 + mi * 16 + half * 8 + qr;
            float zl = Zl[m], zr = Zr[m];
#pragma unroll
            for (int j = 0; j < 4; j++) {
#pragma unroll
                for (int cc = 0; cc < 2; cc++) {
                    int d = n0 + wn * 32 + j * 8 + qc * 2 + cc;
                    C[(size_t)m * FD + d] = X[(size_t)m * FD + d]
                        + accl[mi][j][half * 2 + cc] / zl
                        + accr[mi][j][half * 2 + cc] / zr;
                }
            }
        }
    }
}

// ------ kernel 5: ConvTranspose 2x2 s2 via tf32 mma + fused gate, 3-stage ------
// Also zeroes the BN accumulators (replaces the separate zero_kernel launch).
#define CT_A 1152   // 16*72
#define CT_B 4224   // 16*264
__global__ __launch_bounds__(256, 2) void convt_mma_kernel(
    const float* __restrict__ x, const float* __restrict__ upw,
    const float* __restrict__ upb, const float* __restrict__ s) {
    extern __shared__ unsigned csm[];
    unsigned* Ap = csm;               // 3 * CT_A
    unsigned* Bp = csm + 3 * CT_A;    // 3 * CT_B

    int n = blockIdx.z;
    const float* src = (n == 0) ? x
                     : (n == BB - 1) ? (x + (size_t)(BB - 1) * INC * FD)
                     : (g_mid + (size_t)(n - 1) * INC * FD);
    int m0 = blockIdx.x * 64;
    int n0 = blockIdx.y * 256;

    if (blockIdx.x == 0 && blockIdx.y == 0 && blockIdx.z == 0) {
        g_bnsum[threadIdx.x] = 0.f;
        g_bnsq[threadIdx.x] = 0.f;
    }

    int tid = threadIdx.x;
    int warp = tid >> 5, lane = tid & 31;
    int wm = warp & 1;
    int wn = warp >> 1;
    int qr = lane >> 2;
    int qc = lane & 3;

    int ac = tid >> 4, am4 = (tid & 15) * 4;

    float acc[2][8][4] = {};

    // prologue: chunks 0,1
#pragma unroll
    for (int st = 0; st < 2; st++) {
        unsigned* Ad = Ap + st * CT_A;
        unsigned* Bd = Bp + st * CT_B;
        cpa16(&Ad[ac * 72 + am4], &upw[(size_t)(st * 16 + ac) * 1024 + m0 + am4]);
#pragma unroll
        for (int it = 0; it < 4; it++) {
            int e = it * 256 + tid;
            int cc = e >> 6, c4 = (e & 63) * 4;
            cpa16(&Bd[cc * 264 + c4], &src[(size_t)(st * 16 + cc) * FD + n0 + c4]);
        }
        CP_COMMIT();
    }

    int cs = 0;
    for (int c = 0; c < 32; c++) {
        CP_WAIT1();
        __syncthreads();
        if (c + 2 < 32) {
            int es = cs + 2; if (es >= 3) es -= 3;
            int c0 = (c + 2) * 16;
            unsigned* Ad = Ap + es * CT_A;
            unsigned* Bd = Bp + es * CT_B;
            cpa16(&Ad[ac * 72 + am4], &upw[(size_t)(c0 + ac) * 1024 + m0 + am4]);
#pragma unroll
            for (int it = 0; it < 4; it++) {
                int e = it * 256 + tid;
                int cc = e >> 6, c4 = (e & 63) * 4;
                cpa16(&Bd[cc * 264 + c4], &src[(size_t)(c0 + cc) * FD + n0 + c4]);
            }
        }
        CP_COMMIT();
        const unsigned* As = Ap + cs * CT_A;
        const unsigned* Bs = Bp + cs * CT_B;
#pragma unroll
        for (int k8 = 0; k8 < 2; k8++) {
            unsigned a[2][4];
            int ra0 = (k8 * 8 + qc) * 72;
            int ra1 = (k8 * 8 + qc + 4) * 72;
#pragma unroll
            for (int mi = 0; mi < 2; mi++) {
                int ocb = wm * 32 + mi * 16 + qr;
                a[mi][0] = As[ra0 + ocb];
                a[mi][1] = As[ra0 + ocb + 8];
                a[mi][2] = As[ra1 + ocb];
                a[mi][3] = As[ra1 + ocb + 8];
            }
            int rb0 = (k8 * 8 + qc) * 264 + wn * 64 + qr;
            int rb1 = (k8 * 8 + qc + 4) * 264 + wn * 64 + qr;
#pragma unroll
            for (int j = 0; j < 8; j++) {
                unsigned b[2] = {Bs[rb0 + j * 8], Bs[rb1 + j * 8]};
                mma_tf32(acc[0][j], a[0], b);
                mma_tf32(acc[1][j], a[1], b);
            }
        }
        cs = (cs == 2) ? 0 : cs + 1;
    }
    // epilogue: bias + skip + relu + sigmoid, scatter to g_gate
#pragma unroll
    for (int mi = 0; mi < 2; mi++) {
#pragma unroll
        for (int half = 0; half < 2; half++) {
            int row = m0 + wm * 32 + mi * 16 + half * 8 + qr;
            int o = row >> 2, ab = row & 3, av = ab >> 1, bq = ab & 1;
            float bias = upb[o];
#pragma unroll
            for (int j = 0; j < 8; j++) {
#pragma unroll
                for (int cc = 0; cc < 2; cc++) {
                    int col = n0 + wn * 64 + j * 8 + qc * 2 + cc;
                    int isp = col >> 5, jsp = col & 31;
                    int oy = 2 * isp + av, ox = 2 * jsp + bq;
                    size_t gi = (((size_t)n * OUTC + o) * OH + oy) * OW + ox;
                    float v = acc[mi][j][half * 2 + cc] + bias + s[gi];
                    v = v > 0.f ? v : 0.f;
                    g_gate[gi] = 1.f / (1.f + expf(-v));
                }
            }
        }
    }
}

// ---------------- kernel 6: conv3x3 via tf32 mma, 3-stage cp.async pipeline ----------------
#define PS 744
#define INW (8 * PS)
#define WW_ 4864
__global__ __launch_bounds__(256) void conv_mma_kernel(
    const float* __restrict__ sskip, const float* __restrict__ cw,
    const float* __restrict__ cb) {
    extern __shared__ unsigned dyns[];
    unsigned* inb = dyns;                    // 3 * INW
    unsigned* wb = dyns + 3 * INW;           // 3 * WW_
    float* rs = (float*)(dyns + 3 * INW + 3 * WW_);
    float* rq = rs + 64;

    int n = blockIdx.z;
    int oc0 = blockIdx.y * 64;
    int y0 = blockIdx.x * 8;

    int tid = threadIdx.x;
    int warp = tid >> 5, lane = tid & 31;
    int wn = warp;
    int qr = lane >> 2;
    int qc = lane & 3;

    // halo columns zero for ALL THREE buffers (positions 3 and 68)
    for (int e = tid; e < 480; e += 256) {
        int bsel = e / 160;
        int r2 = e - bsel * 160;
        int r = r2 >> 1;
        int icc = r / 10, yy = r - icc * 10;
        inb[bsel * INW + icc * PS + yy * 72 + ((r2 & 1) ? 68 : 3)] = 0u;
    }
    if (tid < 64) { rs[tid] = 0.f; rq[tid] = 0.f; }

    float acc[4][8][4] = {};

    int seg = (tid & 15) * 4;
    int rbase = tid >> 4;

    // prologue: issue chunks 0,1
#pragma unroll
    for (int st = 0; st < 2; st++) {
        int ic0 = st * 8;
        unsigned* ind = inb + st * INW;
        unsigned* wd = wb + st * WW_;
#pragma unroll
        for (int i = 0; i < 5; i++) {
            int r = rbase + 16 * i;
            int icc = r / 10, yy = r - icc * 10;
            int gy = y0 + yy - 1;
            int ic = ic0 + icc;
            int gyc = gy < 0 ? 0 : (gy > OH - 1 ? OH - 1 : gy);
            const float* srcp = (ic < OUTC)
                ? &g_gate[(((size_t)n * OUTC + ic) * OH + gyc) * OW + seg]
                : &sskip[(((size_t)n * OUTC + (ic - OUTC)) * OH + gyc) * OW + seg];
            int sz = ((unsigned)gy < (unsigned)OH) ? 16 : 0;
            cpa16z(&ind[icc * PS + yy * 72 + 4 + seg], srcp, sz);
        }
#pragma unroll
        for (int i = 0; i < 5; i++) {
            int e = tid + 256 * i;
            if (e < 1152) {
                int oc = e / 18, f = e - oc * 18;
                cpa16(&wd[oc * 76 + f * 4], &cw[(size_t)(oc0 + oc) * (2 * OUTC * 9) + ic0 * 9 + f * 4]);
            }
        }
        CP_COMMIT();
    }

    int cs = 0;
    for (int c = 0; c < 64; c++) {
        CP_WAIT1();
        __syncthreads();
        if (c + 2 < 64) {
            int es = cs + 2; if (es >= 3) es -= 3;
            int ic0 = (c + 2) * 8;
            unsigned* ind = inb + es * INW;
            unsigned* wd = wb + es * WW_;
#pragma unroll
            for (int i = 0; i < 5; i++) {
                int r = rbase + 16 * i;
                int icc = r / 10, yy = r - icc * 10;
                int gy = y0 + yy - 1;
                int ic = ic0 + icc;
                int gyc = gy < 0 ? 0 : (gy > OH - 1 ? OH - 1 : gy);
                const float* srcp = (ic < OUTC)
                    ? &g_gate[(((size_t)n * OUTC + ic) * OH + gyc) * OW + seg]
                    : &sskip[(((size_t)n * OUTC + (ic - OUTC)) * OH + gyc) * OW + seg];
                int sz = ((unsigned)gy < (unsigned)OH) ? 16 : 0;
                cpa16z(&ind[icc * PS + yy * 72 + 4 + seg], srcp, sz);
            }
#pragma unroll
            for (int i = 0; i < 5; i++) {
                int e = tid + 256 * i;
                if (e < 1152) {
                    int oc = e / 18, f = e - oc * 18;
                    cpa16(&wd[oc * 76 + f * 4], &cw[(size_t)(oc0 + oc) * (2 * OUTC * 9) + ic0 * 9 + f * 4]);
                }
            }
        }
        CP_COMMIT();
        const unsigned* in_s = inb + cs * INW;
        const unsigned* w_s = wb + cs * WW_;
#pragma unroll
        for (int ky = 0; ky < 3; ky++) {
            int rowoff = (wn + ky) * 72 + 3;
#pragma unroll
            for (int kx = 0; kx < 3; kx++) {
                int pos = ky * 3 + kx;
                unsigned a[4][4];
#pragma unroll
                for (int mi = 0; mi < 4; mi++) {
                    int ocb = mi * 16 + qr;
                    a[mi][0] = w_s[ocb * 76 + qc * 9 + pos];
                    a[mi][1] = w_s[(ocb + 8) * 76 + qc * 9 + pos];
                    a[mi][2] = w_s[ocb * 76 + (qc + 4) * 9 + pos];
                    a[mi][3] = w_s[(ocb + 8) * 76 + (qc + 4) * 9 + pos];
                }
#pragma unroll
                for (int j = 0; j < 8; j++) {
                    int col = j * 8 + qr + kx;
                    unsigned b[2] = {in_s[qc * PS + rowoff + col],
                                     in_s[(qc + 4) * PS + rowoff + col]};
                    mma_tf32(acc[0][j], a[0], b);
                    mma_tf32(acc[1][j], a[1], b);
                    mma_tf32(acc[2][j], a[2], b);
                    mma_tf32(acc[3][j], a[3], b);
                }
            }
        }
        cs = (cs == 2) ? 0 : cs + 1;
    }

    int row = y0 + wn;
#pragma unroll
    for (int mi = 0; mi < 4; mi++) {
#pragma unroll
        for (int half = 0; half < 2; half++) {
            int ocl = mi * 16 + half * 8 + qr;
            int oc = oc0 + ocl;
            float bias = cb[oc];
            float s0 = 0.f, s1 = 0.f;
#pragma unroll
            for (int j = 0; j < 8; j++) {
#pragma unroll
                for (int cc = 0; cc < 2; cc++) {
                    float v = acc[mi][j][half * 2 + cc] + bias;
                    int col = j * 8 + qc * 2 + cc;
                    g_y[(((size_t)n * OUTC + oc) * OH + row) * OW + col] = v;
                    s0 += v;
                    s1 += v * v;
                }
            }
            s0 += __shfl_xor_sync(0xffffffffu, s0, 1);
            s0 += __shfl_xor_sync(0xffffffffu, s0, 2);
            s1 += __shfl_xor_sync(0xffffffffu, s1, 1);
            s1 += __shfl_xor_sync(0xffffffffu, s1, 2);
            if (qc == 0) {
                atomicAdd(&rs[ocl], s0);
                atomicAdd(&rq[ocl], s1);
            }
        }
    }
    __syncthreads();
    if (tid < 64) {
        atomicAdd(&g_bnsum[oc0 + tid], rs[tid]);
        atomicAdd(&g_bnsq[oc0 + tid], rq[tid]);
    }
}

// ---------------- small kernels ----------------
__global__ void bnstats_kernel(const float* __restrict__ bn_g, const float* __restrict__ bn_b) {
    int c = threadIdx.x;
    float cnt = (float)(BB * OH * OW);
    float mean = g_bnsum[c] / cnt;
    float var = g_bnsq[c] / cnt - mean * mean;
    float inv = rsqrtf(var + 1e-5f);
    float sc = bn_g[c] * inv;
    g_bnscale[c] = sc;
    g_bnshift[c] = bn_b[c] - mean * sc;
}

__global__ void bnorm_kernel(float* __restrict__ out) {
    int i4 = blockIdx.x * blockDim.x + threadIdx.x;
    const int total4 = BB * OUTC * OH * OW / 4;
    if (i4 >= total4) return;
    int base = i4 * 4;
    int oc = (base >> 12) & (OUTC - 1);
    float sc = g_bnscale[oc], sh = g_bnshift[oc];
    float4 v = *(const float4*)&g_y[base];
    float4 r;
    r.x = fmaxf(v.x * sc + sh, 0.f);
    r.y = fmaxf(v.y * sc + sh, 0.f);
    r.z = fmaxf(v.z * sc + sh, 0.f);
    r.w = fmaxf(v.w * sc + sh, 0.f);
    *(float4*)&out[base] = r;
}

// ---------------- launcher ----------------
extern "C" void kernel_launch(void* const* d_in, const int* in_sizes, int n_in,
                              void* d_out, int out_size) {
    const float* x    = (const float*)d_in[0];
    const float* s    = (const float*)d_in[1];
    const float* up_w = (const float*)d_in[2];
    const float* up_b = (const float*)d_in[3];
    const float* wq   = (const float*)d_in[4];
    const float* wkl  = (const float*)d_in[5];
    const float* wkr  = (const float*)d_in[6];
    const float* c1_w = (const float*)d_in[7];
    const float* c1_b = (const float*)d_in[8];
    const float* bn_g = (const float*)d_in[9];
    const float* bn_b = (const float*)d_in[10];
    float* out = (float*)d_out;

    const int conv_smem = (3 * INW + 3 * WW_) * 4 + 128 * 4;      // 130304 B
    const int proj_smem = (4 * PJ_A + 4 * PJ_B) * 4;              // 55296 B
    const int kv_smem   = (3 * KV_A + 3 * KV_B) * 4;              // 64512 B
    const int ao_smem   = (3 * AO_A + 6 * AO_B) * 4;              // 67584 B
    const int cvt_smem  = (3 * CT_A + 3 * CT_B) * 4;              // 64512 B
    cudaFuncSetAttribute(conv_mma_kernel,
                         cudaFuncAttributeMaxDynamicSharedMemorySize, conv_smem);
    cudaFuncSetAttribute(proj_mma_kernel,
                         cudaFuncAttributeMaxDynamicSharedMemorySize, proj_smem);
    cudaFuncSetAttribute(kv_mma_kernel,
                         cudaFuncAttributeMaxDynamicSharedMemorySize, kv_smem);
    cudaFuncSetAttribute(attnout_mma_kernel,
                         cudaFuncAttributeMaxDynamicSharedMemorySize, ao_smem);
    cudaFuncSetAttribute(convt_mma_kernel,
                         cudaFuncAttributeMaxDynamicSharedMemorySize, cvt_smem);

    proj_mma_kernel<<<dim3(8, 1, NS * 3), 256, proj_smem>>>(x, wq, wkl, wkr);
    sumz_kernel<<<dim3(NS, 2), 128>>>();
    kv_mma_kernel<<<dim3(2, 4, NS * 2), 256, kv_smem>>>(x);
    attnout_mma_kernel<<<dim3(8, 8, NS), 256, ao_smem>>>(x);
    convt_mma_kernel<<<dim3(16, 4, BB), 256, cvt_smem>>>(x, up_w, up_b, s);
    conv_mma_kernel<<<dim3(8, 4, BB), 256, conv_smem>>>(s, c1_w, c1_b);
    bnstats_kernel<<<1, OUTC>>>(bn_g, bn_b);
    int total4 = BB * OUTC * OH * OW / 4;
    bnorm_kernel<<<(total4 + 255) / 256, 256>>>(out);
}

// round 17
// speedup vs baseline: 1.1085x; 1.0002x over previous
#include <cuda_runtime.h>
#include <math.h>

#define BB 16
#define INC 512
#define OUTC 256
#define HH 32
#define WW 32
#define FD 1024
#define DK 128
#define NS 14          // interior samples (B-2)
#define OH 64
#define OW 64

// ---------------- scratch (static device memory; no allocation) ----------------
__device__ float g_mid[NS * INC * FD];
__device__ float g_q[NS * INC * DK];
__device__ float g_kl[NS * INC * DK];
__device__ float g_kr[NS * INC * DK];
__device__ float g_kvl[NS * DK * FD];
__device__ float g_kvr[NS * DK * FD];
__device__ float g_z[2 * NS * INC];
__device__ float g_gate[BB * OUTC * OH * OW];
__device__ float g_y[BB * OUTC * OH * OW];
__device__ float g_bnsum[OUTC];
__device__ float g_bnsq[OUTC];
__device__ float g_bnscale[OUTC];
__device__ float g_bnshift[OUTC];

// ---------------- tf32 mma helpers ----------------
// Raw fp32 bit patterns are fed to the tf32 MMA (HW truncates low mantissa).
__device__ __forceinline__ void mma_tf32(float (&d)[4], const unsigned (&a)[4], const unsigned (&b)[2]) {
    asm("mma.sync.aligned.m16n8k8.row.col.f32.tf32.tf32.f32 "
        "{%0,%1,%2,%3}, {%4,%5,%6,%7}, {%8,%9}, {%0,%1,%2,%3};"
        : "+f"(d[0]), "+f"(d[1]), "+f"(d[2]), "+f"(d[3])
        : "r"(a[0]), "r"(a[1]), "r"(a[2]), "r"(a[3]), "r"(b[0]), "r"(b[1]));
}

__device__ __forceinline__ void cpa16(void* d, const void* s) {
    unsigned sa = (unsigned)__cvta_generic_to_shared(d);
    asm volatile("cp.async.cg.shared.global [%0], [%1], 16;" :: "r"(sa), "l"(s));
}
__device__ __forceinline__ void cpa16z(void* d, const void* s, int sz) {
    unsigned sa = (unsigned)__cvta_generic_to_shared(d);
    asm volatile("cp.async.cg.shared.global [%0], [%1], 16, %2;" :: "r"(sa), "l"(s), "r"(sz));
}
#define CP_COMMIT() asm volatile("cp.async.commit_group;")
#define CP_WAIT0()  asm volatile("cp.async.wait_group 0;")
#define CP_WAIT1()  asm volatile("cp.async.wait_group 1;")
#define CP_WAIT2()  asm volatile("cp.async.wait_group 2;")

// ---------------- kernel 1: projections q/kl/kr = phi(A @ W), 4-stage pipeline ----------------
#define PJ_A 1280   // 64*20
#define PJ_B 2176   // 16*136
__global__ __launch_bounds__(256, 2) void proj_mma_kernel(
    const float* __restrict__ x, const float* __restrict__ wq,
    const float* __restrict__ wkl, const float* __restrict__ wkr) {
    extern __shared__ unsigned psm[];
    unsigned* Ap = psm;               // 4 * PJ_A
    unsigned* Bp = psm + 4 * PJ_A;    // 4 * PJ_B

    int zi = blockIdx.z;
    int sample = zi / 3, p = zi % 3;
    const float* A;
    const float* Wm;
    float* C;
    if (p == 0)      { A = x + (size_t)(sample + 1) * INC * FD; Wm = wq;  C = g_q  + (size_t)sample * INC * DK; }
    else if (p == 1) { A = x + (size_t)(sample + 0) * INC * FD; Wm = wkl; C = g_kl + (size_t)sample * INC * DK; }
    else             { A = x + (size_t)(sample + 2) * INC * FD; Wm = wkr; C = g_kr + (size_t)sample * INC * DK; }

    int m0 = blockIdx.x * 64;
    int tid = threadIdx.x;
    int warp = tid >> 5, lane = tid & 31;
    int wm = warp & 3;
    int wn = warp >> 2;
    int qr = lane >> 2, qc = lane & 3;

    int am = tid >> 2, ak4 = (tid & 3) * 4;

    float acc[8][4] = {};

    // prologue: issue chunks 0..2
#pragma unroll
    for (int s = 0; s < 3; s++) {
        unsigned* Ad = Ap + s * PJ_A;
        unsigned* Bd = Bp + s * PJ_B;
        cpa16(&Ad[am * 20 + ak4], &A[(size_t)(m0 + am) * FD + s * 16 + ak4]);
#pragma unroll
        for (int it = 0; it < 2; it++) {
            int e = it * 256 + tid;
            int kk = e >> 5, c4 = (e & 31) * 4;
            cpa16(&Bd[kk * 136 + c4], &Wm[(size_t)(s * 16 + kk) * DK + c4]);
        }
        CP_COMMIT();
    }

    int cs = 0;
    for (int c = 0; c < 64; c++) {
        CP_WAIT2();
        __syncthreads();
        if (c + 3 < 64) {
            int es = cs + 3; if (es >= 4) es -= 4;
            int k0 = (c + 3) * 16;
            unsigned* Ad = Ap + es * PJ_A;
            unsigned* Bd = Bp + es * PJ_B;
            cpa16(&Ad[am * 20 + ak4], &A[(size_t)(m0 + am) * FD + k0 + ak4]);
#pragma unroll
            for (int it = 0; it < 2; it++) {
                int e = it * 256 + tid;
                int kk = e >> 5, c4 = (e & 31) * 4;
                cpa16(&Bd[kk * 136 + c4], &Wm[(size_t)(k0 + kk) * DK + c4]);
            }
        }
        CP_COMMIT();
        const unsigned* As = Ap + cs * PJ_A;
        const unsigned* Bs = Bp + cs * PJ_B;
#pragma unroll
        for (int k8 = 0; k8 < 2; k8++) {
            unsigned a[4];
            int mb = wm * 16 + qr;
            int kb = k8 * 8 + qc;
            a[0] = As[mb * 20 + kb];
            a[1] = As[(mb + 8) * 20 + kb];
            a[2] = As[mb * 20 + kb + 4];
            a[3] = As[(mb + 8) * 20 + kb + 4];
            int rb0 = (k8 * 8 + qc) * 136 + wn * 64 + qr;
            int rb1 = (k8 * 8 + qc + 4) * 136 + wn * 64 + qr;
#pragma unroll
            for (int j = 0; j < 8; j++) {
                unsigned b[2] = {Bs[rb0 + j * 8], Bs[rb1 + j * 8]};
                mma_tf32(acc[j], a, b);
            }
        }
        cs = (cs == 3) ? 0 : cs + 1;
    }
    // epilogue: phi = elu + 1
#pragma unroll
    for (int half = 0; half < 2; half++) {
        int m = m0 + wm * 16 + half * 8 + qr;
#pragma unroll
        for (int j = 0; j < 8; j++) {
#pragma unroll
            for (int cc = 0; cc < 2; cc++) {
                int ncol = wn * 64 + j * 8 + qc * 2 + cc;
                float v = acc[j][half * 2 + cc];
                C[(size_t)m * DK + ncol] = (v > 0.f) ? (v + 1.f) : expf(v);
            }
        }
    }
}

// ---------------- kernel 2: column sums + z = q @ ksum + 1e-6 ----------------
__global__ void sumz_kernel() {
    int sample = blockIdx.x;
    int side = blockIdx.y;
    const float* K = (side == 0 ? g_kl : g_kr) + (size_t)sample * INC * DK;
    const float* Q = g_q + (size_t)sample * INC * DK;
    __shared__ float ssum[DK];
    int t = threadIdx.x;
    float s = 0.f;
    for (int n = 0; n < INC; n++) s += K[n * DK + t];
    ssum[t] = s;
    __syncthreads();
    float* Z = g_z + (size_t)(side * NS + sample) * INC;
    for (int rr = 0; rr < 4; rr++) {
        int row = rr * 128 + t;
        float d = 0.f;
        for (int k = 0; k < DK; k++) d += Q[row * DK + k] * ssum[k];
        Z[row] = d + 1e-6f;
    }
}

// ---------------- kernel 3: kv[k][d] = sum_n K[n][k] * V[n][d], 3-stage pipeline ----------------
#define KV_A 1152   // 16*72
#define KV_B 4224   // 16*264
__global__ __launch_bounds__(256, 2) void kv_mma_kernel(const float* __restrict__ x) {
    extern __shared__ unsigned ksm[];
    unsigned* Ap = ksm;               // 3 * KV_A
    unsigned* Bp = ksm + 3 * KV_A;    // 3 * KV_B

    int zi = blockIdx.z;
    int sample = zi >> 1, side = zi & 1;
    const float* K = (side == 0 ? g_kl : g_kr) + (size_t)sample * INC * DK;
    const float* V = x + (size_t)(sample + (side == 0 ? 0 : 2)) * INC * FD;
    float* C = (side == 0 ? g_kvl : g_kvr) + (size_t)sample * DK * FD;

    int m0 = blockIdx.x * 64;
    int n0 = blockIdx.y * 256;
    int tid = threadIdx.x;
    int warp = tid >> 5, lane = tid & 31;
    int wm = warp & 1, wn = warp >> 1;
    int qr = lane >> 2, qc = lane & 3;

    int an = tid >> 4, ak4 = (tid & 15) * 4;

    float acc[2][8][4] = {};

    // prologue: chunks 0,1
#pragma unroll
    for (int s = 0; s < 2; s++) {
        unsigned* Ad = Ap + s * KV_A;
        unsigned* Bd = Bp + s * KV_B;
        cpa16(&Ad[an * 72 + ak4], &K[(size_t)(s * 16 + an) * DK + m0 + ak4]);
#pragma unroll
        for (int it = 0; it < 4; it++) {
            int e = it * 256 + tid;
            int nn = e >> 6, c4 = (e & 63) * 4;
            cpa16(&Bd[nn * 264 + c4], &V[(size_t)(s * 16 + nn) * FD + n0 + c4]);
        }
        CP_COMMIT();
    }

    int cs = 0;
    for (int c = 0; c < 32; c++) {
        CP_WAIT1();
        __syncthreads();
        if (c + 2 < 32) {
            int es = cs + 2; if (es >= 3) es -= 3;
            int c0 = (c + 2) * 16;
            unsigned* Ad = Ap + es * KV_A;
            unsigned* Bd = Bp + es * KV_B;
            cpa16(&Ad[an * 72 + ak4], &K[(size_t)(c0 + an) * DK + m0 + ak4]);
#pragma unroll
            for (int it = 0; it < 4; it++) {
                int e = it * 256 + tid;
                int nn = e >> 6, c4 = (e & 63) * 4;
                cpa16(&Bd[nn * 264 + c4], &V[(size_t)(c0 + nn) * FD + n0 + c4]);
            }
        }
        CP_COMMIT();
        const unsigned* As = Ap + cs * KV_A;
        const unsigned* Bs = Bp + cs * KV_B;
#pragma unroll
        for (int k8 = 0; k8 < 2; k8++) {
            unsigned a[2][4];
            int ra0 = (k8 * 8 + qc) * 72;
            int ra1 = (k8 * 8 + qc + 4) * 72;
#pragma unroll
            for (int mi = 0; mi < 2; mi++) {
                int mb = wm * 32 + mi * 16 + qr;
                a[mi][0] = As[ra0 + mb];
                a[mi][1] = As[ra0 + mb + 8];
                a[mi][2] = As[ra1 + mb];
                a[mi][3] = As[ra1 + mb + 8];
            }
            int rb0 = (k8 * 8 + qc) * 264 + wn * 64 + qr;
            int rb1 = (k8 * 8 + qc + 4) * 264 + wn * 64 + qr;
#pragma unroll
            for (int j = 0; j < 8; j++) {
                unsigned b[2] = {Bs[rb0 + j * 8], Bs[rb1 + j * 8]};
                mma_tf32(acc[0][j], a[0], b);
                mma_tf32(acc[1][j], a[1], b);
            }
        }
        cs = (cs == 2) ? 0 : cs + 1;
    }
#pragma unroll
    for (int mi = 0; mi < 2; mi++) {
#pragma unroll
        for (int half = 0; half < 2; half++) {
            int m = m0 + wm * 32 + mi * 16 + half * 8 + qr;
#pragma unroll
            for (int j = 0; j < 8; j++) {
#pragma unroll
                for (int cc = 0; cc < 2; cc++) {
                    int d = n0 + wn * 64 + j * 8 + qc * 2 + cc;
                    C[(size_t)m * FD + d] = acc[mi][j][half * 2 + cc];
                }
            }
        }
    }
}

// ------ kernel 4: out = x + (q@kvl)/zl + (q@kvr)/zr, dual-B tf32 mma, 3-stage ------
#define AO_A 1280   // 64*20
#define AO_B 2176   // 16*136
__global__ __launch_bounds__(256, 2) void attnout_mma_kernel(const float* __restrict__ x) {
    extern __shared__ unsigned asm_[];
    unsigned* Ap = asm_;                        // 3 * AO_A
    unsigned* Blp = asm_ + 3 * AO_A;            // 3 * AO_B
    unsigned* Brp = asm_ + 3 * AO_A + 3 * AO_B; // 3 * AO_B

    int sample = blockIdx.z;
    const float* Q = g_q + (size_t)sample * INC * DK;
    const float* KVL = g_kvl + (size_t)sample * DK * FD;
    const float* KVR = g_kvr + (size_t)sample * DK * FD;
    const float* Zl = g_z + (size_t)sample * INC;
    const float* Zr = g_z + (size_t)(NS + sample) * INC;
    const float* X = x + (size_t)(sample + 1) * INC * FD;
    float* C = g_mid + (size_t)sample * INC * FD;

    int m0 = blockIdx.x * 64;
    int n0 = blockIdx.y * 128;
    int tid = threadIdx.x;
    int warp = tid >> 5, lane = tid & 31;
    int wm = warp & 1, wn = warp >> 1;
    int qr = lane >> 2, qc = lane & 3;

    int am = tid >> 2, ak4 = (tid & 3) * 4;

    float accl[2][4][4] = {}, accr[2][4][4] = {};

    // prologue: chunks 0,1
#pragma unroll
    for (int s = 0; s < 2; s++) {
        unsigned* Ad = Ap + s * AO_A;
        unsigned* Bld = Blp + s * AO_B;
        unsigned* Brd = Brp + s * AO_B;
        cpa16(&Ad[am * 20 + ak4], &Q[(size_t)(m0 + am) * DK + s * 16 + ak4]);
#pragma unroll
        for (int it = 0; it < 2; it++) {
            int e = it * 256 + tid;
            int kk = e >> 5, c4 = (e & 31) * 4;
            cpa16(&Bld[kk * 136 + c4], &KVL[(size_t)(s * 16 + kk) * FD + n0 + c4]);
            cpa16(&Brd[kk * 136 + c4], &KVR[(size_t)(s * 16 + kk) * FD + n0 + c4]);
        }
        CP_COMMIT();
    }

    int cs = 0;
    for (int c = 0; c < 8; c++) {
        CP_WAIT1();
        __syncthreads();
        if (c + 2 < 8) {
            int es = cs + 2; if (es >= 3) es -= 3;
            int k0 = (c + 2) * 16;
            unsigned* Ad = Ap + es * AO_A;
            unsigned* Bld = Blp + es * AO_B;
            unsigned* Brd = Brp + es * AO_B;
            cpa16(&Ad[am * 20 + ak4], &Q[(size_t)(m0 + am) * DK + k0 + ak4]);
#pragma unroll
            for (int it = 0; it < 2; it++) {
                int e = it * 256 + tid;
                int kk = e >> 5, c4 = (e & 31) * 4;
                cpa16(&Bld[kk * 136 + c4], &KVL[(size_t)(k0 + kk) * FD + n0 + c4]);
                cpa16(&Brd[kk * 136 + c4], &KVR[(size_t)(k0 + kk) * FD + n0 + c4]);
            }
        }
        CP_COMMIT();
        const unsigned* As = Ap + cs * AO_A;
        const unsigned* Bl = Blp + cs * AO_B;
        const unsigned* Br = Brp + cs * AO_B;
#pragma unroll
        for (int k8 = 0; k8 < 2; k8++) {
            unsigned a[2][4];
            int kb = k8 * 8 + qc;
#pragma unroll
            for (int mi = 0; mi < 2; mi++) {
                int mb = wm * 32 + mi * 16 + qr;
                a[mi][0] = As[mb * 20 + kb];
                a[mi][1] = As[(mb + 8) * 20 + kb];
                a[mi][2] = As[mb * 20 + kb + 4];
                a[mi][3] = As[(mb + 8) * 20 + kb + 4];
            }
            int rb0 = (k8 * 8 + qc) * 136 + wn * 32 + qr;
            int rb1 = (k8 * 8 + qc + 4) * 136 + wn * 32 + qr;
#pragma unroll
            for (int j = 0; j < 4; j++) {
                unsigned bl[2] = {Bl[rb0 + j * 8], Bl[rb1 + j * 8]};
                unsigned br[2] = {Br[rb0 + j * 8], Br[rb1 + j * 8]};
                mma_tf32(accl[0][j], a[0], bl);
                mma_tf32(accl[1][j], a[1], bl);
                mma_tf32(accr[0][j], a[0], br);
                mma_tf32(accr[1][j], a[1], br);
            }
        }
        cs = (cs == 2) ? 0 : cs + 1;
    }
#pragma unroll
    for (int mi = 0; mi < 2; mi++) {
#pragma unroll
        for (int half = 0; half < 2; half++) {
            int m = m0 + wm * 32 + mi * 16 + half * 8 + qr;
            float zl = Zl[m], zr = Zr[m];
#pragma unroll
            for (int j = 0; j < 4; j++) {
#pragma unroll
                for (int cc = 0; cc < 2; cc++) {
                    int d = n0 + wn * 32 + j * 8 + qc * 2 + cc;
                    C[(size_t)m * FD + d] = X[(size_t)m * FD + d]
                        + accl[mi][j][half * 2 + cc] / zl
                        + accr[mi][j][half * 2 + cc] / zr;
                }
            }
        }
    }
}

// ------ kernel 5: ConvTranspose 2x2 s2 via tf32 mma + fused gate, 3-stage ------
// Also zeroes the BN accumulators (replaces the separate zero_kernel launch).
#define CT_A 1152   // 16*72
#define CT_B 4224   // 16*264
__global__ __launch_bounds__(256, 2) void convt_mma_kernel(
    const float* __restrict__ x, const float* __restrict__ upw,
    const float* __restrict__ upb, const float* __restrict__ s) {
    extern __shared__ unsigned csm[];
    unsigned* Ap = csm;               // 3 * CT_A
    unsigned* Bp = csm + 3 * CT_A;    // 3 * CT_B

    int n = blockIdx.z;
    const float* src = (n == 0) ? x
                     : (n == BB - 1) ? (x + (size_t)(BB - 1) * INC * FD)
                     : (g_mid + (size_t)(n - 1) * INC * FD);
    int m0 = blockIdx.x * 64;
    int n0 = blockIdx.y * 256;

    if (blockIdx.x == 0 && blockIdx.y == 0 && blockIdx.z == 0) {
        g_bnsum[threadIdx.x] = 0.f;
        g_bnsq[threadIdx.x] = 0.f;
    }

    int tid = threadIdx.x;
    int warp = tid >> 5, lane = tid & 31;
    int wm = warp & 1;
    int wn = warp >> 1;
    int qr = lane >> 2;
    int qc = lane & 3;

    int ac = tid >> 4, am4 = (tid & 15) * 4;

    float acc[2][8][4] = {};

    // prologue: chunks 0,1
#pragma unroll
    for (int st = 0; st < 2; st++) {
        unsigned* Ad = Ap + st * CT_A;
        unsigned* Bd = Bp + st * CT_B;
        cpa16(&Ad[ac * 72 + am4], &upw[(size_t)(st * 16 + ac) * 1024 + m0 + am4]);
#pragma unroll
        for (int it = 0; it < 4; it++) {
            int e = it * 256 + tid;
            int cc = e >> 6, c4 = (e & 63) * 4;
            cpa16(&Bd[cc * 264 + c4], &src[(size_t)(st * 16 + cc) * FD + n0 + c4]);
        }
        CP_COMMIT();
    }

    int cs = 0;
    for (int c = 0; c < 32; c++) {
        CP_WAIT1();
        __syncthreads();
        if (c + 2 < 32) {
            int es = cs + 2; if (es >= 3) es -= 3;
            int c0 = (c + 2) * 16;
            unsigned* Ad = Ap + es * CT_A;
            unsigned* Bd = Bp + es * CT_B;
            cpa16(&Ad[ac * 72 + am4], &upw[(size_t)(c0 + ac) * 1024 + m0 + am4]);
#pragma unroll
            for (int it = 0; it < 4; it++) {
                int e = it * 256 + tid;
                int cc = e >> 6, c4 = (e & 63) * 4;
                cpa16(&Bd[cc * 264 + c4], &src[(size_t)(c0 + cc) * FD + n0 + c4]);
            }
        }
        CP_COMMIT();
        const unsigned* As = Ap + cs * CT_A;
        const unsigned* Bs = Bp + cs * CT_B;
#pragma unroll
        for (int k8 = 0; k8 < 2; k8++) {
            unsigned a[2][4];
            int ra0 = (k8 * 8 + qc) * 72;
            int ra1 = (k8 * 8 + qc + 4) * 72;
#pragma unroll
            for (int mi = 0; mi < 2; mi++) {
                int ocb = wm * 32 + mi * 16 + qr;
                a[mi][0] = As[ra0 + ocb];
                a[mi][1] = As[ra0 + ocb + 8];
                a[mi][2] = As[ra1 + ocb];
                a[mi][3] = As[ra1 + ocb + 8];
            }
            int rb0 = (k8 * 8 + qc) * 264 + wn * 64 + qr;
            int rb1 = (k8 * 8 + qc + 4) * 264 + wn * 64 + qr;
#pragma unroll
            for (int j = 0; j < 8; j++) {
                unsigned b[2] = {Bs[rb0 + j * 8], Bs[rb1 + j * 8]};
                mma_tf32(acc[0][j], a[0], b);
                mma_tf32(acc[1][j], a[1], b);
            }
        }
        cs = (cs == 2) ? 0 : cs + 1;
    }
    // epilogue: bias + skip + relu + sigmoid, scatter to g_gate
#pragma unroll
    for (int mi = 0; mi < 2; mi++) {
#pragma unroll
        for (int half = 0; half < 2; half++) {
            int row = m0 + wm * 32 + mi * 16 + half * 8 + qr;
            int o = row >> 2, ab = row & 3, av = ab >> 1, bq = ab & 1;
            float bias = upb[o];
#pragma unroll
            for (int j = 0; j < 8; j++) {
#pragma unroll
                for (int cc = 0; cc < 2; cc++) {
                    int col = n0 + wn * 64 + j * 8 + qc * 2 + cc;
                    int isp = col >> 5, jsp = col & 31;
                    int oy = 2 * isp + av, ox = 2 * jsp + bq;
                    size_t gi = (((size_t)n * OUTC + o) * OH + oy) * OW + ox;
                    float v = acc[mi][j][half * 2 + cc] + bias + s[gi];
                    v = v > 0.f ? v : 0.f;
                    g_gate[gi] = 1.f / (1.f + expf(-v));
                }
            }
        }
    }
}

// ---------------- kernel 6: conv3x3 via tf32 mma, 3-stage cp.async pipeline ----------------
#define PS 744
#define INW (8 * PS)
#define WW_ 4864
__global__ __launch_bounds__(256) void conv_mma_kernel(
    const float* __restrict__ sskip, const float* __restrict__ cw,
    const float* __restrict__ cb) {
    extern __shared__ unsigned dyns[];
    unsigned* inb = dyns;                    // 3 * INW
    unsigned* wb = dyns + 3 * INW;           // 3 * WW_
    float* rs = (float*)(dyns + 3 * INW + 3 * WW_);
    float* rq = rs + 64;

    int n = blockIdx.z;
    int oc0 = blockIdx.y * 64;
    int y0 = blockIdx.x * 8;

    int tid = threadIdx.x;
    int warp = tid >> 5, lane = tid & 31;
    int wn = warp;
    int qr = lane >> 2;
    int qc = lane & 3;

    // halo columns zero for ALL THREE buffers (positions 3 and 68)
    for (int e = tid; e < 480; e += 256) {
        int bsel = e / 160;
        int r2 = e - bsel * 160;
        int r = r2 >> 1;
        int icc = r / 10, yy = r - icc * 10;
        inb[bsel * INW + icc * PS + yy * 72 + ((r2 & 1) ? 68 : 3)] = 0u;
    }
    if (tid < 64) { rs[tid] = 0.f; rq[tid] = 0.f; }

    float acc[4][8][4] = {};

    int seg = (tid & 15) * 4;
    int rbase = tid >> 4;

    // prologue: issue chunks 0,1
#pragma unroll
    for (int st = 0; st < 2; st++) {
        int ic0 = st * 8;
        unsigned* ind = inb + st * INW;
        unsigned* wd = wb + st * WW_;
#pragma unroll
        for (int i = 0; i < 5; i++) {
            int r = rbase + 16 * i;
            int icc = r / 10, yy = r - icc * 10;
            int gy = y0 + yy - 1;
            int ic = ic0 + icc;
            int gyc = gy < 0 ? 0 : (gy > OH - 1 ? OH - 1 : gy);
            const float* srcp = (ic < OUTC)
                ? &g_gate[(((size_t)n * OUTC + ic) * OH + gyc) * OW + seg]
                : &sskip[(((size_t)n * OUTC + (ic - OUTC)) * OH + gyc) * OW + seg];
            int sz = ((unsigned)gy < (unsigned)OH) ? 16 : 0;
            cpa16z(&ind[icc * PS + yy * 72 + 4 + seg], srcp, sz);
        }
#pragma unroll
        for (int i = 0; i < 5; i++) {
            int e = tid + 256 * i;
            if (e < 1152) {
                int oc = e / 18, f = e - oc * 18;
                cpa16(&wd[oc * 76 + f * 4], &cw[(size_t)(oc0 + oc) * (2 * OUTC * 9) + ic0 * 9 + f * 4]);
            }
        }
        CP_COMMIT();
    }

    int cs = 0;
    for (int c = 0; c < 64; c++) {
        CP_WAIT1();
        __syncthreads();
        if (c + 2 < 64) {
            int es = cs + 2; if (es >= 3) es -= 3;
            int ic0 = (c + 2) * 8;
            unsigned* ind = inb + es * INW;
            unsigned* wd = wb + es * WW_;
#pragma unroll
            for (int i = 0; i < 5; i++) {
                int r = rbase + 16 * i;
                int icc = r / 10, yy = r - icc * 10;
                int gy = y0 + yy - 1;
                int ic = ic0 + icc;
                int gyc = gy < 0 ? 0 : (gy > OH - 1 ? OH - 1 : gy);
                const float* srcp = (ic < OUTC)
                    ? &g_gate[(((size_t)n * OUTC + ic) * OH + gyc) * OW + seg]
                    : &sskip[(((size_t)n * OUTC + (ic - OUTC)) * OH + gyc) * OW + seg];
                int sz = ((unsigned)gy < (unsigned)OH) ? 16 : 0;
                cpa16z(&ind[icc * PS + yy * 72 + 4 + seg], srcp, sz);
            }
#pragma unroll
            for (int i = 0; i < 5; i++) {
                int e = tid + 256 * i;
                if (e < 1152) {
                    int oc = e / 18, f = e - oc * 18;
                    cpa16(&wd[oc * 76 + f * 4], &cw[(size_t)(oc0 + oc) * (2 * OUTC * 9) + ic0 * 9 + f * 4]);
                }
            }
        }
        CP_COMMIT();
        const unsigned* in_s = inb + cs * INW;
        const unsigned* w_s = wb + cs * WW_;
#pragma unroll
        for (int ky = 0; ky < 3; ky++) {
            int rowoff = (wn + ky) * 72 + 3;
#pragma unroll
            for (int kx = 0; kx < 3; kx++) {
                int pos = ky * 3 + kx;
                unsigned a[4][4];
#pragma unroll
                for (int mi = 0; mi < 4; mi++) {
                    int ocb = mi * 16 + qr;
                    a[mi][0] = w_s[ocb * 76 + qc * 9 + pos];
                    a[mi][1] = w_s[(ocb + 8) * 76 + qc * 9 + pos];
                    a[mi][2] = w_s[ocb * 76 + (qc + 4) * 9 + pos];
                    a[mi][3] = w_s[(ocb + 8) * 76 + (qc + 4) * 9 + pos];
                }
#pragma unroll
                for (int j = 0; j < 8; j++) {
                    int col = j * 8 + qr + kx;
                    unsigned b[2] = {in_s[qc * PS + rowoff + col],
                                     in_s[(qc + 4) * PS + rowoff + col]};
                    mma_tf32(acc[0][j], a[0], b);
                    mma_tf32(acc[1][j], a[1], b);
                    mma_tf32(acc[2][j], a[2], b);
                    mma_tf32(acc[3][j], a[3], b);
                }
            }
        }
        cs = (cs == 2) ? 0 : cs + 1;
    }

    int row = y0 + wn;
#pragma unroll
    for (int mi = 0; mi < 4; mi++) {
#pragma unroll
        for (int half = 0; half < 2; half++) {
            int ocl = mi * 16 + half * 8 + qr;
            int oc = oc0 + ocl;
            float bias = cb[oc];
            float s0 = 0.f, s1 = 0.f;
#pragma unroll
            for (int j = 0; j < 8; j++) {
#pragma unroll
                for (int cc = 0; cc < 2; cc++) {
                    float v = acc[mi][j][half * 2 + cc] + bias;
                    int col = j * 8 + qc * 2 + cc;
                    g_y[(((size_t)n * OUTC + oc) * OH + row) * OW + col] = v;
                    s0 += v;
                    s1 += v * v;
                }
            }
            s0 += __shfl_xor_sync(0xffffffffu, s0, 1);
            s0 += __shfl_xor_sync(0xffffffffu, s0, 2);
            s1 += __shfl_xor_sync(0xffffffffu, s1, 1);
            s1 += __shfl_xor_sync(0xffffffffu, s1, 2);
            if (qc == 0) {
                atomicAdd(&rs[ocl], s0);
                atomicAdd(&rq[ocl], s1);
            }
        }
    }
    __syncthreads();
    if (tid < 64) {
        atomicAdd(&g_bnsum[oc0 + tid], rs[tid]);
        atomicAdd(&g_bnsq[oc0 + tid], rq[tid]);
    }
}

// ---------------- small kernels ----------------
__global__ void bnstats_kernel(const float* __restrict__ bn_g, const float* __restrict__ bn_b) {
    int c = threadIdx.x;
    float cnt = (float)(BB * OH * OW);
    float mean = g_bnsum[c] / cnt;
    float var = g_bnsq[c] / cnt - mean * mean;
    float inv = rsqrtf(var + 1e-5f);
    float sc = bn_g[c] * inv;
    g_bnscale[c] = sc;
    g_bnshift[c] = bn_b[c] - mean * sc;
}

__global__ void bnorm_kernel(float* __restrict__ out) {
    int i4 = blockIdx.x * blockDim.x + threadIdx.x;
    const int total4 = BB * OUTC * OH * OW / 4;
    if (i4 >= total4) return;
    int base = i4 * 4;
    int oc = (base >> 12) & (OUTC - 1);
    float sc = g_bnscale[oc], sh = g_bnshift[oc];
    float4 v = *(const float4*)&g_y[base];
    float4 r;
    r.x = fmaxf(v.x * sc + sh, 0.f);
    r.y = fmaxf(v.y * sc + sh, 0.f);
    r.z = fmaxf(v.z * sc + sh, 0.f);
    r.w = fmaxf(v.w * sc + sh, 0.f);
    *(float4*)&out[base] = r;
}

// ---------------- launcher ----------------
extern "C" void kernel_launch(void* const* d_in, const int* in_sizes, int n_in,
                              void* d_out, int out_size) {
    const float* x    = (const float*)d_in[0];
    const float* s    = (const float*)d_in[1];
    const float* up_w = (const float*)d_in[2];
    const float* up_b = (const float*)d_in[3];
    const float* wq   = (const float*)d_in[4];
    const float* wkl  = (const float*)d_in[5];
    const float* wkr  = (const float*)d_in[6];
    const float* c1_w = (const float*)d_in[7];
    const float* c1_b = (const float*)d_in[8];
    const float* bn_g = (const float*)d_in[9];
    const float* bn_b = (const float*)d_in[10];
    float* out = (float*)d_out;

    const int conv_smem = (3 * INW + 3 * WW_) * 4 + 128 * 4;      // 130304 B
    const int proj_smem = (4 * PJ_A + 4 * PJ_B) * 4;              // 55296 B
    const int kv_smem   = (3 * KV_A + 3 * KV_B) * 4;              // 64512 B
    const int ao_smem   = (3 * AO_A + 6 * AO_B) * 4;              // 67584 B
    const int cvt_smem  = (3 * CT_A + 3 * CT_B) * 4;              // 64512 B
    cudaFuncSetAttribute(conv_mma_kernel,
                         cudaFuncAttributeMaxDynamicSharedMemorySize, conv_smem);
    cudaFuncSetAttribute(proj_mma_kernel,
                         cudaFuncAttributeMaxDynamicSharedMemorySize, proj_smem);
    cudaFuncSetAttribute(kv_mma_kernel,
                         cudaFuncAttributeMaxDynamicSharedMemorySize, kv_smem);
    cudaFuncSetAttribute(attnout_mma_kernel,
                         cudaFuncAttributeMaxDynamicSharedMemorySize, ao_smem);
    cudaFuncSetAttribute(convt_mma_kernel,
                         cudaFuncAttributeMaxDynamicSharedMemorySize, cvt_smem);

    proj_mma_kernel<<<dim3(8, 1, NS * 3), 256, proj_smem>>>(x, wq, wkl, wkr);
    sumz_kernel<<<dim3(NS, 2), 128>>>();
    kv_mma_kernel<<<dim3(2, 4, NS * 2), 256, kv_smem>>>(x);
    attnout_mma_kernel<<<dim3(8, 8, NS), 256, ao_smem>>>(x);
    convt_mma_kernel<<<dim3(16, 4, BB), 256, cvt_smem>>>(x, up_w, up_b, s);
    conv_mma_kernel<<<dim3(8, 4, BB), 256, conv_smem>>>(s, c1_w, c1_b);
    bnstats_kernel<<<1, OUTC>>>(bn_g, bn_b);
    int total4 = BB * OUTC * OH * OW / 4;
    bnorm_kernel<<<(total4 + 255) / 256, 256>>>(out);
}